// round 7
// baseline (speedup 1.0000x reference)
#include <cuda_runtime.h>
#include <cuda_fp16.h>
#include <cuda_bf16.h>
#include <math.h>
#include <stdint.h>

#define B 4096
#define D 256
#define NR 4
#define TEMP_INV 10.0f
#define TILE 128
#define NBLK 32                          // B / TILE
#define NTRI (NBLK * (NBLK + 1) / 2)     // 528 upper-tri tiles
#define SROW 20                          // smem row stride in floats (80 B)
#define LOG2E 1.4426950408889634f
#define LN2   0.6931471805599453f
#define MFIX  10.0f                      // fixed LSE max: sim in [-10,10]

// -------- scratch ----------------------------------------------------------
__device__ __nv_bfloat16 g_pn[B * D];    // bf16 normalized projections (2 MB)
__device__ __half g_sim[(size_t)B * B];  // similarity, fp16 (32 MB; upper tiles)
__device__ float g_ps[NBLK * B];         // per (tile-slot, row) masked exp-sums
__device__ float g_lse[B];
__device__ float g_acc[8];
__device__ unsigned g_bar_u;             // grid barrier / finalize counter

// -------- helpers ----------------------------------------------------------
__device__ __forceinline__ float ex2a(float x) {
    float y; asm("ex2.approx.f32 %0, %1;" : "=f"(y) : "f"(x)); return y;
}
__device__ __forceinline__ float lg2a(float x) {
    float y; asm("lg2.approx.f32 %0, %1;" : "=f"(y) : "f"(x)); return y;
}

__device__ __forceinline__ void mma_bf16(float c[4], const uint32_t a[4],
                                         uint32_t b0, uint32_t b1) {
    asm volatile(
        "mma.sync.aligned.m16n8k16.row.col.f32.bf16.bf16.f32 "
        "{%0,%1,%2,%3}, {%4,%5,%6,%7}, {%8,%9}, {%0,%1,%2,%3};\n"
        : "+f"(c[0]), "+f"(c[1]), "+f"(c[2]), "+f"(c[3])
        : "r"(a[0]), "r"(a[1]), "r"(a[2]), "r"(a[3]), "r"(b0), "r"(b1));
}

__device__ __forceinline__ void ldsm4(uint32_t& r0, uint32_t& r1, uint32_t& r2,
                                      uint32_t& r3, uint32_t addr) {
    asm volatile("ldmatrix.sync.aligned.m8n8.x4.shared.b16 {%0,%1,%2,%3}, [%4];\n"
                 : "=r"(r0), "=r"(r1), "=r"(r2), "=r"(r3) : "r"(addr));
}

__device__ __forceinline__ void cp16(uint32_t smem_dst, const void* gsrc) {
    asm volatile("cp.async.ca.shared.global [%0], [%1], 16;\n" :: "r"(smem_dst), "l"(gsrc));
}
#define CP_COMMIT() asm volatile("cp.async.commit_group;\n" ::: "memory")
#define CP_WAIT(n)  asm volatile("cp.async.wait_group %0;\n" :: "n"(n) : "memory")

__device__ __forceinline__ void tri_decode(int idx, int& bi, int& bj) {
    int k = idx, r = 0;
#pragma unroll 1
    while (k >= NBLK - r) { k -= NBLK - r; r++; }
    bi = r; bj = r + k;
}

// grid-wide barrier: all blocks resident (grid = 2*SMs, launch_bounds(256,2))
__device__ __forceinline__ void gsync(unsigned target) {
    __syncthreads();
    if (threadIdx.x == 0) {
        __threadfence();
        atomicAdd(&g_bar_u, 1u);
        while (*((volatile unsigned*)&g_bar_u) < target) __nanosleep(32);
        __threadfence();
    }
    __syncthreads();
}

// ===========================================================================
__global__ __launch_bounds__(256, 2) void mega_kernel(
    const float* __restrict__ proj, const float* __restrict__ logits,
    const float* __restrict__ rp, const int* __restrict__ labels,
    float* __restrict__ out) {
    __shared__ float sA[2][TILE * SROW];   // 20 KB (bf16 tiles, 80B row stride)
    __shared__ float sB[2][TILE * SROW];   // 20 KB
    __shared__ int   lA[TILE], lB[TILE];
    __shared__ float red[4][TILE];         // sim reductions / pair lse cache
    __shared__ float sh[256];

    const int t = threadIdx.x, lane = t & 31, warp = t >> 5;
    const int nb = gridDim.x, blk = blockIdx.x;
    const int wr = warp & 3, wc = warp >> 2;
    const int tig = lane & 3, grp = lane >> 2;

    // ---------------- phase 0a: normalize -> bf16 --------------------------
    for (int row = blk * 8 + warp; row < B; row += nb * 8) {
        const float4* p4 = (const float4*)(proj + (size_t)row * D);
        float4 v1 = p4[lane], v2 = p4[32 + lane];
        float ss = v1.x * v1.x + v1.y * v1.y + v1.z * v1.z + v1.w * v1.w
                 + v2.x * v2.x + v2.y * v2.y + v2.z * v2.z + v2.w * v2.w;
#pragma unroll
        for (int o = 16; o > 0; o >>= 1) ss += __shfl_xor_sync(0xFFFFFFFFu, ss, o);
        float inv = 1.0f / fmaxf(sqrtf(ss), 1e-12f);
        union { __nv_bfloat162 h2[2]; uint2 u2; } cv1, cv2;
        cv1.h2[0] = __floats2bfloat162_rn(v1.x * inv, v1.y * inv);
        cv1.h2[1] = __floats2bfloat162_rn(v1.z * inv, v1.w * inv);
        cv2.h2[0] = __floats2bfloat162_rn(v2.x * inv, v2.y * inv);
        cv2.h2[1] = __floats2bfloat162_rn(v2.z * inv, v2.w * inv);
        uint2* dst = (uint2*)(g_pn + (size_t)row * D);
        dst[lane] = cv1.u2;
        dst[32 + lane] = cv2.u2;
    }

    // ---------------- phase 0b: focal + region (approx math) ---------------
    {
        float focal = 0, Spd = 0, Sct = 0, ce_sum = 0, cpd = 0, cct = 0;
        int b = blk + nb * t;
        if (b < B) {
            int y = labels[b];
            float z0 = logits[2 * b] * (LOG2E / 1.5f), z1 = logits[2 * b + 1] * (LOG2E / 1.5f);
            float m  = fmaxf(z0, z1);                       // log2 domain
            float l2 = m + lg2a(ex2a(z0 - m) + ex2a(z1 - m));
            float ce = (l2 - (y ? z1 : z0)) * LN2;
            float pt = ex2a(-ce * LOG2E);
            float om = 1.0f - pt;
            focal = om * om * ce;
            if (y) cpd = 1.0f; else cct = 1.0f;

            float p[NR][2], le[NR][2], ent[NR];
#pragma unroll
            for (int r = 0; r < NR; r++) {
                float a0 = rp[((size_t)r * B + b) * 2] * LOG2E;
                float a1 = rp[((size_t)r * B + b) * 2 + 1] * LOG2E;
                float mm = fmaxf(a0, a1);
                float ll = mm + lg2a(ex2a(a0 - mm) + ex2a(a1 - mm));
                float lp0 = (a0 - ll) * LN2, lp1 = (a1 - ll) * LN2;  // natural-log probs
                p[r][0] = ex2a(a0 - ll);
                p[r][1] = ex2a(a1 - ll);
                le[r][0] = lg2a(p[r][0] + 1e-10f) * LN2;
                le[r][1] = lg2a(p[r][1] + 1e-10f) * LN2;
                ent[r] = p[r][0] * lp0 + p[r][1] * lp1;
                ce_sum += -(y ? lp1 : lp0);
            }
            float S = 0.0f;
#pragma unroll
            for (int i = 0; i < NR; i++)
#pragma unroll
                for (int j = i + 1; j < NR; j++)
                    S += ent[j] - (p[j][0] * le[i][0] + p[j][1] * le[i][1]);
            if (y) Spd = S; else Sct = S;
        }
        // 6 block reductions via sh
        float vals[6] = {focal, cpd, cct, Spd, Sct, ce_sum};
#pragma unroll
        for (int a = 0; a < 6; a++) {
            sh[t] = vals[a];
            __syncthreads();
            for (int s = 128; s > 0; s >>= 1) {
                if (t < s) sh[t] += sh[t + s];
                __syncthreads();
            }
            if (t == 0 && sh[0] != 0.0f) atomicAdd(&g_acc[a], sh[0]);
            __syncthreads();
        }
    }

    gsync(nb);   // g_pn + small-loss accumulators ready

    // ---------------- phase A: sim GEMM tiles ------------------------------
    uint32_t uA = (uint32_t)__cvta_generic_to_shared(&sA[0][0]);
    uint32_t uB = (uint32_t)__cvta_generic_to_shared(&sB[0][0]);
    int laneRow   = lane & 15;
    int laneChunk = (lane >> 4) * 16;
    uint32_t aBase = uA + (uint32_t)((wr * 32 + laneRow) * 80 + laneChunk);
    uint32_t bBase = uB + (uint32_t)((wc * 64 + laneRow) * 80 + laneChunk);
    const uint32_t STG = TILE * 80;
    int ldr0 = t >> 2, ldc0 = t & 3;
    uint32_t dA0 = uA + (uint32_t)(ldr0 * 80 + ldc0 * 16);
    uint32_t dA1 = dA0 + 64 * 80;
    uint32_t dB0 = dA0 - uA + uB, dB1 = dA1 - uA + uB;

    for (int tile = blk; tile < NTRI; tile += nb) {
        int bi, bj;
        tri_decode(tile, bi, bj);
        int rowA = bi * TILE, rowB = bj * TILE;

        if (t < TILE) lA[t] = labels[rowA + t];
        else          lB[t - TILE] = labels[rowB + (t - TILE)];

        float c[2][8][4];
#pragma unroll
        for (int mt = 0; mt < 2; mt++)
#pragma unroll
            for (int nt = 0; nt < 8; nt++)
#pragma unroll
                for (int q = 0; q < 4; q++) c[mt][nt][q] = 0.0f;

#define LOAD_STAGE(st, k0)                                                               \
    {                                                                                    \
        cp16(dA0 + (st) * STG, &g_pn[(size_t)(rowA + ldr0) * D + (k0) + ldc0 * 8]);      \
        cp16(dB0 + (st) * STG, &g_pn[(size_t)(rowB + ldr0) * D + (k0) + ldc0 * 8]);      \
        cp16(dA1 + (st) * STG, &g_pn[(size_t)(rowA + 64 + ldr0) * D + (k0) + ldc0 * 8]); \
        cp16(dB1 + (st) * STG, &g_pn[(size_t)(rowB + 64 + ldr0) * D + (k0) + ldc0 * 8]); \
    }

        LOAD_STAGE(0, 0);
        CP_COMMIT();

        for (int kt = 0; kt < D / 32; kt++) {
            uint32_t cs = (kt & 1) * STG;
            if (kt + 1 < D / 32) {
                LOAD_STAGE((kt + 1) & 1, (kt + 1) * 32);
                CP_COMMIT();
                CP_WAIT(1);
            } else {
                CP_WAIT(0);
            }
            __syncthreads();
#pragma unroll
            for (int ks = 0; ks < 2; ks++) {
                uint32_t ko = cs + ks * 32;
                uint32_t a[2][4];
                ldsm4(a[0][0], a[0][1], a[0][2], a[0][3], aBase + ko);
                ldsm4(a[1][0], a[1][1], a[1][2], a[1][3], aBase + ko + 16 * 80);
#pragma unroll
                for (int ntp = 0; ntp < 4; ntp++) {
                    uint32_t b0, b1, b2, b3;
                    ldsm4(b0, b1, b2, b3, bBase + ko + (uint32_t)(ntp * 16 * 80));
                    mma_bf16(c[0][2 * ntp],     a[0], b0, b2);
                    mma_bf16(c[0][2 * ntp + 1], a[0], b1, b3);
                    mma_bf16(c[1][2 * ntp],     a[1], b0, b2);
                    mma_bf16(c[1][2 * ntp + 1], a[1], b1, b3);
                }
            }
            __syncthreads();
        }
#undef LOAD_STAGE

#pragma unroll
        for (int mt = 0; mt < 2; mt++)
#pragma unroll
            for (int nt = 0; nt < 8; nt++)
#pragma unroll
                for (int q = 0; q < 4; q++) c[mt][nt][q] *= TEMP_INV;

        if (bi == bj) {
#pragma unroll
            for (int mt = 0; mt < 2; mt++) {
                int gi0 = wr * 32 + mt * 16 + grp;
#pragma unroll
                for (int nt = 0; nt < 8; nt++) {
                    int gj = wc * 64 + nt * 8 + 2 * tig;
                    if (gi0 == gj)         c[mt][nt][0] = -1e9f;
                    if (gi0 == gj + 1)     c[mt][nt][1] = -1e9f;
                    if (gi0 + 8 == gj)     c[mt][nt][2] = -1e9f;
                    if (gi0 + 8 == gj + 1) c[mt][nt][3] = -1e9f;
                }
            }
        }

#pragma unroll
        for (int mt = 0; mt < 2; mt++) {
            int gi0 = rowA + wr * 32 + mt * 16 + grp;
#pragma unroll
            for (int nt = 0; nt < 8; nt++) {
                int gj = rowB + wc * 64 + nt * 8 + 2 * tig;
                *(__half2*)&g_sim[(size_t)gi0 * B + gj] =
                    __floats2half2_rn(c[mt][nt][0], c[mt][nt][1]);
                *(__half2*)&g_sim[(size_t)(gi0 + 8) * B + gj] =
                    __floats2half2_rn(c[mt][nt][2], c[mt][nt][3]);
            }
        }

        // masked-exp partial sums, both directions
        float colacc[16];
#pragma unroll
        for (int k = 0; k < 16; k++) colacc[k] = 0.0f;

#pragma unroll
        for (int mt = 0; mt < 2; mt++) {
#pragma unroll
            for (int rr = 0; rr < 2; rr++) {
                int rloc = wr * 32 + mt * 16 + rr * 8 + grp;
                int labr = lA[rloc];
                float ra = 0.0f;
#pragma unroll
                for (int nt = 0; nt < 8; nt++) {
#pragma unroll
                    for (int q = 0; q < 2; q++) {
                        int cloc = wc * 64 + nt * 8 + 2 * tig + q;
                        float v = c[mt][nt][rr * 2 + q];
                        float e = ex2a((v - MFIX) * LOG2E);
                        e = (lB[cloc] != labr) ? e : 0.0f;
                        ra += e;
                        colacc[nt * 2 + q] += e;
                    }
                }
                ra += __shfl_xor_sync(0xFFFFFFFFu, ra, 1);
                ra += __shfl_xor_sync(0xFFFFFFFFu, ra, 2);
                if (tig == 0) red[wc][rloc] = ra;
            }
        }
        __syncthreads();
        if (t < TILE) g_ps[bj * B + rowA + t] = red[0][t] + red[1][t];

        if (bi < bj) {
            __syncthreads();
#pragma unroll
            for (int k = 0; k < 16; k++) {
                colacc[k] += __shfl_xor_sync(0xFFFFFFFFu, colacc[k], 4);
                colacc[k] += __shfl_xor_sync(0xFFFFFFFFu, colacc[k], 8);
                colacc[k] += __shfl_xor_sync(0xFFFFFFFFu, colacc[k], 16);
            }
            if (grp == 0) {
#pragma unroll
                for (int nt = 0; nt < 8; nt++)
#pragma unroll
                    for (int q = 0; q < 2; q++) {
                        int cloc = wc * 64 + nt * 8 + 2 * tig + q;
                        red[wr][cloc] = colacc[nt * 2 + q];
                    }
            }
            __syncthreads();
            if (t < TILE)
                g_ps[bi * B + rowB + t] =
                    red[0][t] + red[1][t] + red[2][t] + red[3][t];
        }
        __syncthreads();   // protect lA/lB + red for next tile
    }

    gsync(2 * nb);   // all sim tiles + partials done

    // ---------------- phase B: lse per row ---------------------------------
    for (int i = blk * 256 + t; i < B; i += nb * 256) {
        float S = 0.0f;
#pragma unroll 4
        for (int k = 0; k < NBLK; k++) S += g_ps[k * B + i];
        g_lse[i] = MFIX + lg2a(S) * LN2;
    }

    gsync(3 * nb);   // g_lse ready

    // ---------------- phase C: positive-pair sum ---------------------------
    float pacc = 0.0f;
    for (int tile = blk; tile < NTRI; tile += nb) {
        int bi, bj;
        tri_decode(tile, bi, bj);
        int rowA = bi * TILE, rowB = bj * TILE;

        if (t < TILE) { lA[t] = labels[rowA + t]; red[0][t] = g_lse[rowA + t]; }
        else {
            int u = t - TILE;
            lB[u] = labels[rowB + u]; red[1][u] = g_lse[rowB + u];
        }
        __syncthreads();

        int r = t >> 1;
        int cbase = (t & 1) * 64;
        int la = lA[r];
        float lsa = red[0][r];
        int dcol = (bi == bj) ? r : -1;
        bool off = (bi < bj);

        const uint4* rowp = (const uint4*)&g_sim[(size_t)(rowA + r) * B + rowB + cbase];
        float prod = 1.0f;

#pragma unroll
        for (int k = 0; k < 8; k++) {
            uint4 u = rowp[k];
            int c0 = cbase + 8 * k;
            uint32_t uu[4] = {u.x, u.y, u.z, u.w};
            int4   lb0 = *(const int4*)&lB[c0];
            int4   lb1 = *(const int4*)&lB[c0 + 4];
            float4 ls0 = *(const float4*)&red[1][c0];
            float4 ls1 = *(const float4*)&red[1][c0 + 4];
            int   lbv[8] = {lb0.x, lb0.y, lb0.z, lb0.w, lb1.x, lb1.y, lb1.z, lb1.w};
            float lsb[8] = {ls0.x, ls0.y, ls0.z, ls0.w, ls1.x, ls1.y, ls1.z, ls1.w};
            float sv[8];
#pragma unroll
            for (int h = 0; h < 4; h++) {
                float2 f = __half22float2(*(const __half2*)&uu[h]);
                sv[2 * h] = f.x; sv[2 * h + 1] = f.y;
            }
#pragma unroll
            for (int q = 0; q < 8; q++) {
                bool m = (la == lbv[q]) && (c0 + q != dcol);
                if (m) {
                    float s = sv[q];
                    float x1 = lsa - s;
                    pacc += fmaxf(x1, 0.0f);
                    float e1 = ex2a(-LOG2E * fabsf(x1));
                    prod = fmaf(prod, e1, prod);
                    if (off) {
                        float x2 = lsb[q] - s;
                        pacc += fmaxf(x2, 0.0f);
                        float e2 = ex2a(-LOG2E * fabsf(x2));
                        prod = fmaf(prod, e2, prod);
                    }
                }
            }
            if (k & 1) { pacc += lg2a(prod) * LN2; prod = 1.0f; }
        }
        __syncthreads();   // lA/lB/red reuse for next tile
    }

    // block reduce + single atomic
    sh[t] = pacc;
    __syncthreads();
    for (int s = 128; s > 0; s >>= 1) {
        if (t < s) sh[t] += sh[t + s];
        __syncthreads();
    }
    if (t == 0) {
        if (sh[0] != 0.0f) atomicAdd(&g_acc[6], sh[0]);
        __threadfence();
        unsigned c = atomicAdd(&g_bar_u, 1u);
        if (c == 4u * (unsigned)nb - 1u) {     // last arrival: finalize
            volatile float* a = g_acc;
            float focal = a[0] / (float)B;
            float pd_cnt = a[1], ct_cnt = a[2];
            float pd = (pd_cnt > 0.0f) ? a[3] / pd_cnt : 0.0f;
            float ct = (ct_cnt > 0.0f) ? a[4] / ct_cnt : 0.0f;
            float ce = a[5] / (float)B;
            float reg = (pd + ct + ce) / ((float)(NR * (NR - 1)) * 0.5f + (float)NR);
            float cont = a[6] / (float)B;
            out[0] = 1.0f * focal + 0.5f * cont + 0.3f * reg;
#pragma unroll
            for (int k = 0; k < 8; k++) g_acc[k] = 0.0f;
            g_bar_u = 0u;                      // reset for next graph replay
        }
    }
}

// -------- launch -----------------------------------------------------------
extern "C" void kernel_launch(void* const* d_in, const int* in_sizes, int n_in,
                              void* d_out, int out_size) {
    const float* logits = (const float*)d_in[0];
    const float* proj   = (const float*)d_in[1];
    const float* rp     = (const float*)d_in[2];
    const int*   labels = (const int*)d_in[3];
    float* out = (float*)d_out;
    (void)in_sizes; (void)n_in; (void)out_size;

    int dev = 0, nsm = 148;
    cudaGetDevice(&dev);
    cudaDeviceGetAttribute(&nsm, cudaDevAttrMultiProcessorCount, dev);

    mega_kernel<<<2 * nsm, 256>>>(proj, logits, rp, labels, out);
}

// round 8
// speedup vs baseline: 1.0997x; 1.0997x over previous
#include <cuda_runtime.h>
#include <cuda_fp16.h>
#include <cuda_bf16.h>
#include <math.h>
#include <stdint.h>

#define B 4096
#define D 256
#define NR 4
#define TEMP_INV 10.0f
#define TILE 128
#define NBLK 32                          // B / TILE
#define NTRI (NBLK * (NBLK + 1) / 2)     // 528 upper-tri tiles
#define SROW 20                          // smem row stride in floats (80 B)
#define LOG2E 1.4426950408889634f
#define LN2   0.6931471805599453f
#define MFIX  10.0f                      // fixed LSE max: sim in [-10,10]

// -------- scratch ----------------------------------------------------------
__device__ __nv_bfloat16 g_pn[B * D];    // bf16 normalized projections (2 MB)
__device__ __half g_sim[(size_t)B * B];  // similarity, fp16 (upper tiles)
__device__ float g_ps[B * NBLK];         // [row][slot] masked exp-sums (transposed!)
__device__ float g_acc[8];
__device__ unsigned g_done;

// -------- helpers ----------------------------------------------------------
__device__ __forceinline__ float block_reduce_sum(float v, float* sh) {
    int t = threadIdx.x;
    sh[t] = v;
    __syncthreads();
    for (int s = blockDim.x >> 1; s > 0; s >>= 1) {
        if (t < s) sh[t] += sh[t + s];
        __syncthreads();
    }
    float r = sh[0];
    __syncthreads();
    return r;
}

__device__ __forceinline__ float ex2a(float x) {
    float y; asm("ex2.approx.f32 %0, %1;" : "=f"(y) : "f"(x)); return y;
}
__device__ __forceinline__ float lg2a(float x) {
    float y; asm("lg2.approx.f32 %0, %1;" : "=f"(y) : "f"(x)); return y;
}

__device__ __forceinline__ void mma_bf16(float c[4], const uint32_t a[4],
                                         uint32_t b0, uint32_t b1) {
    asm volatile(
        "mma.sync.aligned.m16n8k16.row.col.f32.bf16.bf16.f32 "
        "{%0,%1,%2,%3}, {%4,%5,%6,%7}, {%8,%9}, {%0,%1,%2,%3};\n"
        : "+f"(c[0]), "+f"(c[1]), "+f"(c[2]), "+f"(c[3])
        : "r"(a[0]), "r"(a[1]), "r"(a[2]), "r"(a[3]), "r"(b0), "r"(b1));
}

__device__ __forceinline__ void ldsm4(uint32_t& r0, uint32_t& r1, uint32_t& r2,
                                      uint32_t& r3, uint32_t addr) {
    asm volatile("ldmatrix.sync.aligned.m8n8.x4.shared.b16 {%0,%1,%2,%3}, [%4];\n"
                 : "=r"(r0), "=r"(r1), "=r"(r2), "=r"(r3) : "r"(addr));
}

__device__ __forceinline__ void cp16(uint32_t smem_dst, const void* gsrc) {
    asm volatile("cp.async.ca.shared.global [%0], [%1], 16;\n" :: "r"(smem_dst), "l"(gsrc));
}
#define CP_COMMIT() asm volatile("cp.async.commit_group;\n" ::: "memory")
#define CP_WAIT(n)  asm volatile("cp.async.wait_group %0;\n" :: "n"(n) : "memory")

__device__ __forceinline__ void tri_decode(int idx, int& bi, int& bj) {
    int k = idx, r = 0;
#pragma unroll 1
    while (k >= NBLK - r) { k -= NBLK - r; r++; }
    bi = r; bj = r + k;
}

// -------- 1: prep = normalize (vectorized) + focal/region (approx math) ----
__global__ __launch_bounds__(256) void prep_kernel(const float* __restrict__ proj,
                                                   const float* __restrict__ logits,
                                                   const float* __restrict__ rp,
                                                   const int* __restrict__ labels) {
    {
        int row  = blockIdx.x * 8 + (threadIdx.x >> 5);
        int lane = threadIdx.x & 31;
        const float4* p4 = (const float4*)(proj + (size_t)row * D);
        float4 v1 = p4[lane], v2 = p4[32 + lane];
        float ss = v1.x * v1.x + v1.y * v1.y + v1.z * v1.z + v1.w * v1.w
                 + v2.x * v2.x + v2.y * v2.y + v2.z * v2.z + v2.w * v2.w;
#pragma unroll
        for (int o = 16; o > 0; o >>= 1) ss += __shfl_xor_sync(0xFFFFFFFFu, ss, o);
        float inv = 1.0f / fmaxf(sqrtf(ss), 1e-12f);
        union { __nv_bfloat162 h2[2]; uint2 u2; } cv1, cv2;
        cv1.h2[0] = __floats2bfloat162_rn(v1.x * inv, v1.y * inv);
        cv1.h2[1] = __floats2bfloat162_rn(v1.z * inv, v1.w * inv);
        cv2.h2[0] = __floats2bfloat162_rn(v2.x * inv, v2.y * inv);
        cv2.h2[1] = __floats2bfloat162_rn(v2.z * inv, v2.w * inv);
        uint2* dst = (uint2*)(g_pn + (size_t)row * D);
        dst[lane] = cv1.u2;
        dst[32 + lane] = cv2.u2;
    }

    if (blockIdx.x < 16) {
        int b = blockIdx.x * 256 + threadIdx.x;
        int y = labels[b];
        // focal in log2 domain with approx MUFU
        float z0 = logits[2 * b] * (LOG2E / 1.5f), z1 = logits[2 * b + 1] * (LOG2E / 1.5f);
        float m  = fmaxf(z0, z1);
        float l2 = m + lg2a(ex2a(z0 - m) + ex2a(z1 - m));
        float ce = (l2 - (y ? z1 : z0)) * LN2;
        float pt = ex2a(-ce * LOG2E);
        float om = 1.0f - pt;
        float focal = om * om * ce;
        float cpd = y ? 1.0f : 0.0f, cct = y ? 0.0f : 1.0f;

        float p[NR][2], le[NR][2], ent[NR];
        float ce_sum = 0.0f;
#pragma unroll
        for (int r = 0; r < NR; r++) {
            float a0 = rp[((size_t)r * B + b) * 2] * LOG2E;
            float a1 = rp[((size_t)r * B + b) * 2 + 1] * LOG2E;
            float mm = fmaxf(a0, a1);
            float ll = mm + lg2a(ex2a(a0 - mm) + ex2a(a1 - mm));
            float lp0 = (a0 - ll) * LN2, lp1 = (a1 - ll) * LN2;
            p[r][0] = ex2a(a0 - ll);
            p[r][1] = ex2a(a1 - ll);
            le[r][0] = lg2a(p[r][0] + 1e-10f) * LN2;
            le[r][1] = lg2a(p[r][1] + 1e-10f) * LN2;
            ent[r] = p[r][0] * lp0 + p[r][1] * lp1;
            ce_sum += -(y ? lp1 : lp0);
        }
        float S = 0.0f;
#pragma unroll
        for (int i = 0; i < NR; i++)
#pragma unroll
            for (int j = i + 1; j < NR; j++)
                S += ent[j] - (p[j][0] * le[i][0] + p[j][1] * le[i][1]);
        float Spd = y ? S : 0.0f, Sct = y ? 0.0f : S;

        __shared__ float sh[256];
        float t;
        t = block_reduce_sum(focal, sh);  if (threadIdx.x == 0) atomicAdd(&g_acc[0], t);
        t = block_reduce_sum(cpd, sh);    if (threadIdx.x == 0) atomicAdd(&g_acc[1], t);
        t = block_reduce_sum(cct, sh);    if (threadIdx.x == 0) atomicAdd(&g_acc[2], t);
        t = block_reduce_sum(Spd, sh);    if (threadIdx.x == 0) atomicAdd(&g_acc[3], t);
        t = block_reduce_sum(Sct, sh);    if (threadIdx.x == 0) atomicAdd(&g_acc[4], t);
        t = block_reduce_sum(ce_sum, sh); if (threadIdx.x == 0) atomicAdd(&g_acc[5], t);
    }
}

// -------- 2: sim GEMM (bf16 m16n8k16 + ldmatrix + cp.async) + exp sums -----
__global__ __launch_bounds__(256) void sim_kernel(const int* __restrict__ labels) {
    int bi, bj;
    tri_decode(blockIdx.x, bi, bj);

    __shared__ float sA[2][TILE * SROW];
    __shared__ float sB[2][TILE * SROW];
    __shared__ int   lA[TILE], lB[TILE];
    __shared__ float red_s[4][TILE];

    int t = threadIdx.x, lane = t & 31, warp = t >> 5;
    int wr = warp & 3, wc = warp >> 2;
    int tig = lane & 3, grp = lane >> 2;
    int rowA = bi * TILE, rowB = bj * TILE;

    if (t < TILE) lA[t] = labels[rowA + t];
    else          lB[t - TILE] = labels[rowB + (t - TILE)];

    uint32_t uA = (uint32_t)__cvta_generic_to_shared(&sA[0][0]);
    uint32_t uB = (uint32_t)__cvta_generic_to_shared(&sB[0][0]);
    int laneRow   = lane & 15;
    int laneChunk = (lane >> 4) * 16;
    uint32_t aBase = uA + (uint32_t)((wr * 32 + laneRow) * 80 + laneChunk);
    uint32_t bBase = uB + (uint32_t)((wc * 64 + laneRow) * 80 + laneChunk);
    const uint32_t STG = TILE * 80;

    int ldr0 = t >> 2, ldc0 = t & 3;
    uint32_t dA0 = uA + (uint32_t)(ldr0 * 80 + ldc0 * 16);
    uint32_t dA1 = dA0 + 64 * 80;
    uint32_t dB0 = dA0 - uA + uB, dB1 = dA1 - uA + uB;

    float c[2][8][4];
#pragma unroll
    for (int mt = 0; mt < 2; mt++)
#pragma unroll
        for (int nt = 0; nt < 8; nt++)
#pragma unroll
            for (int q = 0; q < 4; q++) c[mt][nt][q] = 0.0f;

#define LOAD_STAGE(st, k0)                                                               \
    {                                                                                    \
        cp16(dA0 + (st) * STG, &g_pn[(size_t)(rowA + ldr0) * D + (k0) + ldc0 * 8]);      \
        cp16(dB0 + (st) * STG, &g_pn[(size_t)(rowB + ldr0) * D + (k0) + ldc0 * 8]);      \
        cp16(dA1 + (st) * STG, &g_pn[(size_t)(rowA + 64 + ldr0) * D + (k0) + ldc0 * 8]); \
        cp16(dB1 + (st) * STG, &g_pn[(size_t)(rowB + 64 + ldr0) * D + (k0) + ldc0 * 8]); \
    }

    LOAD_STAGE(0, 0);
    CP_COMMIT();

    for (int kt = 0; kt < D / 32; kt++) {
        uint32_t cs = (kt & 1) * STG;
        if (kt + 1 < D / 32) {
            LOAD_STAGE((kt + 1) & 1, (kt + 1) * 32);
            CP_COMMIT();
            CP_WAIT(1);
        } else {
            CP_WAIT(0);
        }
        __syncthreads();
#pragma unroll
        for (int ks = 0; ks < 2; ks++) {
            uint32_t ko = cs + ks * 32;
            uint32_t a[2][4];
            ldsm4(a[0][0], a[0][1], a[0][2], a[0][3], aBase + ko);
            ldsm4(a[1][0], a[1][1], a[1][2], a[1][3], aBase + ko + 16 * 80);
#pragma unroll
            for (int ntp = 0; ntp < 4; ntp++) {
                uint32_t b0, b1, b2, b3;
                ldsm4(b0, b1, b2, b3, bBase + ko + (uint32_t)(ntp * 16 * 80));
                mma_bf16(c[0][2 * ntp],     a[0], b0, b2);
                mma_bf16(c[0][2 * ntp + 1], a[0], b1, b3);
                mma_bf16(c[1][2 * ntp],     a[1], b0, b2);
                mma_bf16(c[1][2 * ntp + 1], a[1], b1, b3);
            }
        }
        __syncthreads();
    }
#undef LOAD_STAGE

#pragma unroll
    for (int mt = 0; mt < 2; mt++)
#pragma unroll
        for (int nt = 0; nt < 8; nt++)
#pragma unroll
            for (int q = 0; q < 4; q++) c[mt][nt][q] *= TEMP_INV;

    if (bi == bj) {
#pragma unroll
        for (int mt = 0; mt < 2; mt++) {
            int gi0 = wr * 32 + mt * 16 + grp;
#pragma unroll
            for (int nt = 0; nt < 8; nt++) {
                int gj = wc * 64 + nt * 8 + 2 * tig;
                if (gi0 == gj)         c[mt][nt][0] = -1e9f;
                if (gi0 == gj + 1)     c[mt][nt][1] = -1e9f;
                if (gi0 + 8 == gj)     c[mt][nt][2] = -1e9f;
                if (gi0 + 8 == gj + 1) c[mt][nt][3] = -1e9f;
            }
        }
    }

#pragma unroll
    for (int mt = 0; mt < 2; mt++) {
        int gi0 = rowA + wr * 32 + mt * 16 + grp;
#pragma unroll
        for (int nt = 0; nt < 8; nt++) {
            int gj = rowB + wc * 64 + nt * 8 + 2 * tig;
            *(__half2*)&g_sim[(size_t)gi0 * B + gj] =
                __floats2half2_rn(c[mt][nt][0], c[mt][nt][1]);
            *(__half2*)&g_sim[(size_t)(gi0 + 8) * B + gj] =
                __floats2half2_rn(c[mt][nt][2], c[mt][nt][3]);
        }
    }

    // masked-exp partial sums, both directions; g_ps is [row][slot]
    float colacc[16];
#pragma unroll
    for (int k = 0; k < 16; k++) colacc[k] = 0.0f;

#pragma unroll
    for (int mt = 0; mt < 2; mt++) {
#pragma unroll
        for (int rr = 0; rr < 2; rr++) {
            int rloc = wr * 32 + mt * 16 + rr * 8 + grp;
            int labr = lA[rloc];
            float ra = 0.0f;
#pragma unroll
            for (int nt = 0; nt < 8; nt++) {
#pragma unroll
                for (int q = 0; q < 2; q++) {
                    int cloc = wc * 64 + nt * 8 + 2 * tig + q;
                    float v = c[mt][nt][rr * 2 + q];
                    float e = ex2a((v - MFIX) * LOG2E);
                    e = (lB[cloc] != labr) ? e : 0.0f;
                    ra += e;
                    colacc[nt * 2 + q] += e;
                }
            }
            ra += __shfl_xor_sync(0xFFFFFFFFu, ra, 1);
            ra += __shfl_xor_sync(0xFFFFFFFFu, ra, 2);
            if (tig == 0) red_s[wc][rloc] = ra;
        }
    }
    __syncthreads();
    if (t < TILE) g_ps[(rowA + t) * NBLK + bj] = red_s[0][t] + red_s[1][t];

    if (bi < bj) {
        __syncthreads();
#pragma unroll
        for (int k = 0; k < 16; k++) {
            colacc[k] += __shfl_xor_sync(0xFFFFFFFFu, colacc[k], 4);
            colacc[k] += __shfl_xor_sync(0xFFFFFFFFu, colacc[k], 8);
            colacc[k] += __shfl_xor_sync(0xFFFFFFFFu, colacc[k], 16);
        }
        if (grp == 0) {
#pragma unroll
            for (int nt = 0; nt < 8; nt++)
#pragma unroll
                for (int q = 0; q < 2; q++) {
                    int cloc = wc * 64 + nt * 8 + 2 * tig + q;
                    red_s[wr][cloc] = colacc[nt * 2 + q];
                }
        }
        __syncthreads();
        if (t < TILE)
            g_ps[(rowB + t) * NBLK + bi] =
                red_s[0][t] + red_s[1][t] + red_s[2][t] + red_s[3][t];
    }
}

// -------- 3: pair sum (fp16 sim, coalesced lse rebuild) + fused finalize ---
__global__ __launch_bounds__(256) void pair_kernel(const int* __restrict__ labels,
                                                   float* __restrict__ out) {
    int bi, bj;
    tri_decode(blockIdx.x, bi, bj);
    int rowA = bi * TILE, rowB = bj * TILE;

    __shared__ float lseA[TILE], lseB[TILE];
    __shared__ int   lA[TILE], lB[TILE];
    int t = threadIdx.x;

    // prologue: lse_i = 10 + log2(sum of 32 consecutive slots) * ln2
    {
        int half_ = t >> 7;
        int u = t & 127;
        int gi = (half_ ? rowB : rowA) + u;
        const float4* p = (const float4*)&g_ps[gi * NBLK];
        float4 a0 = p[0], a1 = p[1], a2 = p[2], a3 = p[3];
        float4 a4 = p[4], a5 = p[5], a6 = p[6], a7 = p[7];
        float S = (((a0.x + a0.y) + (a0.z + a0.w)) + ((a1.x + a1.y) + (a1.z + a1.w)))
                + (((a2.x + a2.y) + (a2.z + a2.w)) + ((a3.x + a3.y) + (a3.z + a3.w)))
                + (((a4.x + a4.y) + (a4.z + a4.w)) + ((a5.x + a5.y) + (a5.z + a5.w)))
                + (((a6.x + a6.y) + (a6.z + a6.w)) + ((a7.x + a7.y) + (a7.z + a7.w)));
        float lse = MFIX + lg2a(S) * LN2;
        if (half_) { lseB[u] = lse; lB[u] = labels[gi]; }
        else       { lseA[u] = lse; lA[u] = labels[gi]; }
    }
    __syncthreads();

    int r = t >> 1;
    int cbase = (t & 1) * 64;
    int la = lA[r];
    float lsa = lseA[r];
    int dcol = (bi == bj) ? r : -1;
    bool off = (bi < bj);

    const uint4* rowp = (const uint4*)&g_sim[(size_t)(rowA + r) * B + rowB + cbase];
    float acc = 0.0f, prod = 1.0f;

#pragma unroll
    for (int k = 0; k < 8; k++) {
        uint4 u = rowp[k];
        int c0 = cbase + 8 * k;
        uint32_t uu[4] = {u.x, u.y, u.z, u.w};
        int4   lb0 = *(const int4*)&lB[c0];
        int4   lb1 = *(const int4*)&lB[c0 + 4];
        float4 ls0 = *(const float4*)&lseB[c0];
        float4 ls1 = *(const float4*)&lseB[c0 + 4];
        int   lbv[8] = {lb0.x, lb0.y, lb0.z, lb0.w, lb1.x, lb1.y, lb1.z, lb1.w};
        float lsb[8] = {ls0.x, ls0.y, ls0.z, ls0.w, ls1.x, ls1.y, ls1.z, ls1.w};
        float sv[8];
#pragma unroll
        for (int h = 0; h < 4; h++) {
            float2 f = __half22float2(*(const __half2*)&uu[h]);
            sv[2 * h] = f.x; sv[2 * h + 1] = f.y;
        }
#pragma unroll
        for (int q = 0; q < 8; q++) {
            bool m = (la == lbv[q]) && (c0 + q != dcol);
            if (m) {
                float s = sv[q];
                float x1 = lsa - s;
                acc += fmaxf(x1, 0.0f);
                float e1 = ex2a(-LOG2E * fabsf(x1));
                prod = fmaf(prod, e1, prod);
                if (off) {
                    float x2 = lsb[q] - s;
                    acc += fmaxf(x2, 0.0f);
                    float e2 = ex2a(-LOG2E * fabsf(x2));
                    prod = fmaf(prod, e2, prod);
                }
            }
        }
        if (k & 1) { acc += lg2a(prod) * LN2; prod = 1.0f; }
    }

    __shared__ float sh[256];
    float tot = block_reduce_sum(acc, sh);
    if (t == 0) {
        atomicAdd(&g_acc[6], tot);
        __threadfence();
        unsigned done = atomicAdd(&g_done, 1u);
        if (done == NTRI - 1) {
            volatile float* a = g_acc;
            float focal = a[0] / (float)B;
            float pd_cnt = a[1], ct_cnt = a[2];
            float pd = (pd_cnt > 0.0f) ? a[3] / pd_cnt : 0.0f;
            float ct = (ct_cnt > 0.0f) ? a[4] / ct_cnt : 0.0f;
            float ce = a[5] / (float)B;
            float reg = (pd + ct + ce) / ((float)(NR * (NR - 1)) * 0.5f + (float)NR);
            float cont = a[6] / (float)B;
            out[0] = 1.0f * focal + 0.5f * cont + 0.3f * reg;
#pragma unroll
            for (int k = 0; k < 8; k++) g_acc[k] = 0.0f;
            g_done = 0u;
        }
    }
}

// -------- launch -----------------------------------------------------------
extern "C" void kernel_launch(void* const* d_in, const int* in_sizes, int n_in,
                              void* d_out, int out_size) {
    const float* logits = (const float*)d_in[0];
    const float* proj   = (const float*)d_in[1];
    const float* rp     = (const float*)d_in[2];
    const int*   labels = (const int*)d_in[3];
    float* out = (float*)d_out;
    (void)in_sizes; (void)n_in; (void)out_size;

    prep_kernel<<<B / 8, 256>>>(proj, logits, rp, labels);
    sim_kernel<<<NTRI, 256>>>(labels);
    pair_kernel<<<NTRI, 256>>>(labels, out);
}

// round 10
// speedup vs baseline: 1.4953x; 1.3598x over previous
#include <cuda_runtime.h>
#include <cuda_bf16.h>
#include <math.h>
#include <stdint.h>

#define B 4096
#define D 256
#define NR 4
#define TEMP_INV 10.0f
#define TILE 128
#define NBLK 32                          // B / TILE
#define NTRI (NBLK * (NBLK + 1) / 2)     // 528 upper-tri tiles
#define LOG2E 1.4426950408889634f
#define LN2   0.6931471805599453f
#define MFIX  10.0f                      // fixed LSE max: sim in [-10,10]

// -------- scratch ----------------------------------------------------------
__device__ __nv_bfloat16 g_pn[B * D];    // bf16 normalized projections (2 MB)
__device__ float g_ps[NBLK * B];         // [slot][row] negative exp-sums
__device__ float g_pp[NBLK * B];         // [slot][row] positive exp-sums
__device__ float g_acc[8];               // 0 focal,1 pd,2 ct,3 Spd,4 Sct,5 ce,6 contA,7 ssum
__device__ unsigned g_done;

// -------- helpers ----------------------------------------------------------
__device__ __forceinline__ float block_reduce_sum(float v, float* sh) {
    int t = threadIdx.x;
    sh[t] = v;
    __syncthreads();
    for (int s = blockDim.x >> 1; s > 0; s >>= 1) {
        if (t < s) sh[t] += sh[t + s];
        __syncthreads();
    }
    float r = sh[0];
    __syncthreads();
    return r;
}

__device__ __forceinline__ float ex2a(float x) {
    float y; asm("ex2.approx.f32 %0, %1;" : "=f"(y) : "f"(x)); return y;
}
__device__ __forceinline__ float lg2a(float x) {
    float y; asm("lg2.approx.f32 %0, %1;" : "=f"(y) : "f"(x)); return y;
}

__device__ __forceinline__ void mma_bf16(float c[4], const uint32_t a[4],
                                         uint32_t b0, uint32_t b1) {
    asm volatile(
        "mma.sync.aligned.m16n8k16.row.col.f32.bf16.bf16.f32 "
        "{%0,%1,%2,%3}, {%4,%5,%6,%7}, {%8,%9}, {%0,%1,%2,%3};\n"
        : "+f"(c[0]), "+f"(c[1]), "+f"(c[2]), "+f"(c[3])
        : "r"(a[0]), "r"(a[1]), "r"(a[2]), "r"(a[3]), "r"(b0), "r"(b1));
}

__device__ __forceinline__ void ldsm4(uint32_t& r0, uint32_t& r1, uint32_t& r2,
                                      uint32_t& r3, uint32_t addr) {
    asm volatile("ldmatrix.sync.aligned.m8n8.x4.shared.b16 {%0,%1,%2,%3}, [%4];\n"
                 : "=r"(r0), "=r"(r1), "=r"(r2), "=r"(r3) : "r"(addr));
}

__device__ __forceinline__ void cp16(uint32_t smem_dst, const void* gsrc) {
    asm volatile("cp.async.ca.shared.global [%0], [%1], 16;\n" :: "r"(smem_dst), "l"(gsrc));
}
#define CP_COMMIT() asm volatile("cp.async.commit_group;\n" ::: "memory")
#define CP_WAIT(n)  asm volatile("cp.async.wait_group %0;\n" :: "n"(n) : "memory")

__device__ __forceinline__ void tri_decode(int idx, int& bi, int& bj) {
    int k = idx, r = 0;
#pragma unroll 1
    while (k >= NBLK - r) { k -= NBLK - r; r++; }
    bi = r; bj = r + k;
}

// -------- 1: prep = normalize (2 rows/warp, batched loads) + focal/region --
__global__ __launch_bounds__(256) void prep_kernel(const float* __restrict__ proj,
                                                   const float* __restrict__ logits,
                                                   const float* __restrict__ rp,
                                                   const int* __restrict__ labels) {
    {
        int warp = threadIdx.x >> 5, lane = threadIdx.x & 31;
        int rowA = blockIdx.x * 16 + warp;       // rows blk*16 + {0..7}
        int rowB = rowA + 8;                     // rows blk*16 + {8..15}
        const float4* pa = (const float4*)(proj + (size_t)rowA * D);
        const float4* pb = (const float4*)(proj + (size_t)rowB * D);
        float4 a1 = pa[lane], a2 = pa[32 + lane];
        float4 b1 = pb[lane], b2 = pb[32 + lane];
        float sa = a1.x * a1.x + a1.y * a1.y + a1.z * a1.z + a1.w * a1.w
                 + a2.x * a2.x + a2.y * a2.y + a2.z * a2.z + a2.w * a2.w;
        float sb = b1.x * b1.x + b1.y * b1.y + b1.z * b1.z + b1.w * b1.w
                 + b2.x * b2.x + b2.y * b2.y + b2.z * b2.z + b2.w * b2.w;
#pragma unroll
        for (int o = 16; o > 0; o >>= 1) {
            sa += __shfl_xor_sync(0xFFFFFFFFu, sa, o);
            sb += __shfl_xor_sync(0xFFFFFFFFu, sb, o);
        }
        float ia = 1.0f / fmaxf(sqrtf(sa), 1e-12f);
        float ib = 1.0f / fmaxf(sqrtf(sb), 1e-12f);
        union { __nv_bfloat162 h2[2]; uint2 u2; } c1, c2, c3, c4;
        c1.h2[0] = __floats2bfloat162_rn(a1.x * ia, a1.y * ia);
        c1.h2[1] = __floats2bfloat162_rn(a1.z * ia, a1.w * ia);
        c2.h2[0] = __floats2bfloat162_rn(a2.x * ia, a2.y * ia);
        c2.h2[1] = __floats2bfloat162_rn(a2.z * ia, a2.w * ia);
        c3.h2[0] = __floats2bfloat162_rn(b1.x * ib, b1.y * ib);
        c3.h2[1] = __floats2bfloat162_rn(b1.z * ib, b1.w * ib);
        c4.h2[0] = __floats2bfloat162_rn(b2.x * ib, b2.y * ib);
        c4.h2[1] = __floats2bfloat162_rn(b2.z * ib, b2.w * ib);
        uint2* da = (uint2*)(g_pn + (size_t)rowA * D);
        uint2* db = (uint2*)(g_pn + (size_t)rowB * D);
        da[lane] = c1.u2; da[32 + lane] = c2.u2;
        db[lane] = c3.u2; db[32 + lane] = c4.u2;
    }

    if (blockIdx.x < 16) {
        int b = blockIdx.x * 256 + threadIdx.x;
        int y = labels[b];
        float z0 = logits[2 * b] * (LOG2E / 1.5f), z1 = logits[2 * b + 1] * (LOG2E / 1.5f);
        float m  = fmaxf(z0, z1);
        float l2 = m + lg2a(ex2a(z0 - m) + ex2a(z1 - m));
        float ce = (l2 - (y ? z1 : z0)) * LN2;
        float pt = ex2a(-ce * LOG2E);
        float om = 1.0f - pt;
        float focal = om * om * ce;
        float cpd = y ? 1.0f : 0.0f, cct = y ? 0.0f : 1.0f;

        float p[NR][2], le[NR][2], ent[NR];
        float ce_sum = 0.0f;
#pragma unroll
        for (int r = 0; r < NR; r++) {
            float a0 = rp[((size_t)r * B + b) * 2] * LOG2E;
            float a1 = rp[((size_t)r * B + b) * 2 + 1] * LOG2E;
            float mm = fmaxf(a0, a1);
            float ll = mm + lg2a(ex2a(a0 - mm) + ex2a(a1 - mm));
            float lp0 = (a0 - ll) * LN2, lp1 = (a1 - ll) * LN2;
            p[r][0] = ex2a(a0 - ll);
            p[r][1] = ex2a(a1 - ll);
            le[r][0] = lg2a(p[r][0] + 1e-10f) * LN2;
            le[r][1] = lg2a(p[r][1] + 1e-10f) * LN2;
            ent[r] = p[r][0] * lp0 + p[r][1] * lp1;
            ce_sum += -(y ? lp1 : lp0);
        }
        float S = 0.0f;
#pragma unroll
        for (int i = 0; i < NR; i++)
#pragma unroll
            for (int j = i + 1; j < NR; j++)
                S += ent[j] - (p[j][0] * le[i][0] + p[j][1] * le[i][1]);
        float Spd = y ? S : 0.0f, Sct = y ? 0.0f : S;

        __shared__ float sh[256];
        float t;
        t = block_reduce_sum(focal, sh);  if (threadIdx.x == 0) atomicAdd(&g_acc[0], t);
        t = block_reduce_sum(cpd, sh);    if (threadIdx.x == 0) atomicAdd(&g_acc[1], t);
        t = block_reduce_sum(cct, sh);    if (threadIdx.x == 0) atomicAdd(&g_acc[2], t);
        t = block_reduce_sum(Spd, sh);    if (threadIdx.x == 0) atomicAdd(&g_acc[3], t);
        t = block_reduce_sum(Sct, sh);    if (threadIdx.x == 0) atomicAdd(&g_acc[4], t);
        t = block_reduce_sum(ce_sum, sh); if (threadIdx.x == 0) atomicAdd(&g_acc[5], t);
    }
}

// -------- 2: sim GEMM + N/P exp-sum epilogue (no sim matrix stored!) -------
__global__ __launch_bounds__(256, 2) void sim_kernel(const int* __restrict__ labels) {
    int bi, bj;
    tri_decode(blockIdx.x, bi, bj);

    __shared__ float sA[2][TILE * 20];
    __shared__ float sB[2][TILE * 20];
    __shared__ int   lA[TILE], lB[TILE];
    __shared__ float red_n[4][TILE], red_p[4][TILE];

    int t = threadIdx.x, lane = t & 31, warp = t >> 5;
    int wr = warp & 3, wc = warp >> 2;
    int tig = lane & 3, grp = lane >> 2;
    int rowA = bi * TILE, rowB = bj * TILE;

    if (t < TILE) lA[t] = labels[rowA + t];
    else          lB[t - TILE] = labels[rowB + (t - TILE)];

    uint32_t uA = (uint32_t)__cvta_generic_to_shared(&sA[0][0]);
    uint32_t uB = (uint32_t)__cvta_generic_to_shared(&sB[0][0]);
    int laneRow   = lane & 15;
    int laneChunk = (lane >> 4) * 16;
    uint32_t aBase = uA + (uint32_t)((wr * 32 + laneRow) * 80 + laneChunk);
    uint32_t bBase = uB + (uint32_t)((wc * 64 + laneRow) * 80 + laneChunk);
    const uint32_t STG = TILE * 80;

    int ldr0 = t >> 2, ldc0 = t & 3;
    uint32_t dA0 = uA + (uint32_t)(ldr0 * 80 + ldc0 * 16);
    uint32_t dA1 = dA0 + 64 * 80;
    uint32_t dB0 = dA0 - uA + uB, dB1 = dA1 - uA + uB;

    float c[2][8][4];
#pragma unroll
    for (int mt = 0; mt < 2; mt++)
#pragma unroll
        for (int nt = 0; nt < 8; nt++)
#pragma unroll
            for (int q = 0; q < 4; q++) c[mt][nt][q] = 0.0f;

#define LOAD_STAGE(st, k0)                                                               \
    {                                                                                    \
        cp16(dA0 + (st) * STG, &g_pn[(size_t)(rowA + ldr0) * D + (k0) + ldc0 * 8]);      \
        cp16(dB0 + (st) * STG, &g_pn[(size_t)(rowB + ldr0) * D + (k0) + ldc0 * 8]);      \
        cp16(dA1 + (st) * STG, &g_pn[(size_t)(rowA + 64 + ldr0) * D + (k0) + ldc0 * 8]); \
        cp16(dB1 + (st) * STG, &g_pn[(size_t)(rowB + 64 + ldr0) * D + (k0) + ldc0 * 8]); \
    }

    LOAD_STAGE(0, 0);
    CP_COMMIT();

    for (int kt = 0; kt < D / 32; kt++) {
        uint32_t cs = (kt & 1) * STG;
        if (kt + 1 < D / 32) {
            LOAD_STAGE((kt + 1) & 1, (kt + 1) * 32);
            CP_COMMIT();
            CP_WAIT(1);
        } else {
            CP_WAIT(0);
        }
        __syncthreads();
#pragma unroll
        for (int ks = 0; ks < 2; ks++) {
            uint32_t ko = cs + ks * 32;
            uint32_t a[2][4];
            ldsm4(a[0][0], a[0][1], a[0][2], a[0][3], aBase + ko);
            ldsm4(a[1][0], a[1][1], a[1][2], a[1][3], aBase + ko + 16 * 80);
#pragma unroll
            for (int ntp = 0; ntp < 4; ntp++) {
                uint32_t b0, b1, b2, b3;
                ldsm4(b0, b1, b2, b3, bBase + ko + (uint32_t)(ntp * 16 * 80));
                mma_bf16(c[0][2 * ntp],     a[0], b0, b2);
                mma_bf16(c[0][2 * ntp + 1], a[0], b1, b3);
                mma_bf16(c[1][2 * ntp],     a[1], b0, b2);
                mma_bf16(c[1][2 * ntp + 1], a[1], b1, b3);
            }
        }
        __syncthreads();
    }
#undef LOAD_STAGE

    // scale + diagonal mask
#pragma unroll
    for (int mt = 0; mt < 2; mt++)
#pragma unroll
        for (int nt = 0; nt < 8; nt++)
#pragma unroll
            for (int q = 0; q < 4; q++) c[mt][nt][q] *= TEMP_INV;

    if (bi == bj) {
#pragma unroll
        for (int mt = 0; mt < 2; mt++) {
            int gi0 = wr * 32 + mt * 16 + grp;
#pragma unroll
            for (int nt = 0; nt < 8; nt++) {
                int gj = wc * 64 + nt * 8 + 2 * tig;
                if (gi0 == gj)         c[mt][nt][0] = -1e9f;
                if (gi0 == gj + 1)     c[mt][nt][1] = -1e9f;
                if (gi0 + 8 == gj)     c[mt][nt][2] = -1e9f;
                if (gi0 + 8 == gj + 1) c[mt][nt][3] = -1e9f;
            }
        }
    }

    // ---- epilogue: route exp(s-10) to N (negatives) or P (positives), ----
    // ---- plus scalar sum of s over positives (ordered weight) -------------
    float colN[16], colP[16];
#pragma unroll
    for (int k = 0; k < 16; k++) { colN[k] = 0.0f; colP[k] = 0.0f; }
    float ssum = 0.0f;

#pragma unroll
    for (int mt = 0; mt < 2; mt++) {
#pragma unroll
        for (int rr = 0; rr < 2; rr++) {
            int rloc = wr * 32 + mt * 16 + rr * 8 + grp;
            int labr = lA[rloc];
            float rn = 0.0f, rp_ = 0.0f;
#pragma unroll
            for (int nt = 0; nt < 8; nt++) {
#pragma unroll
                for (int q = 0; q < 2; q++) {
                    int cloc = wc * 64 + nt * 8 + 2 * tig + q;
                    float v = c[mt][nt][rr * 2 + q];
                    float e = ex2a((v - MFIX) * LOG2E);   // 0 at diag (v=-1e9)
                    bool pos = (lB[cloc] == labr);
                    int idx = nt * 2 + q;
                    if (pos) {
                        rp_ += e; colP[idx] += e;
                        if (v > -1e8f) ssum += v;          // exclude diag
                    } else {
                        rn += e; colN[idx] += e;
                    }
                }
            }
            rn  += __shfl_xor_sync(0xFFFFFFFFu, rn, 1);
            rn  += __shfl_xor_sync(0xFFFFFFFFu, rn, 2);
            rp_ += __shfl_xor_sync(0xFFFFFFFFu, rp_, 1);
            rp_ += __shfl_xor_sync(0xFFFFFFFFu, rp_, 2);
            if (tig == 0) { red_n[wc][rloc] = rn; red_p[wc][rloc] = rp_; }
        }
    }

    // scalar s-sum: warp reduce + one atomic per warp (ordered weight)
    {
        float w = (bi < bj) ? 2.0f : 1.0f;
#pragma unroll
        for (int o = 16; o > 0; o >>= 1) ssum += __shfl_xor_sync(0xFFFFFFFFu, ssum, o);
        if (lane == 0 && ssum != 0.0f) atomicAdd(&g_acc[7], w * ssum);
    }

    __syncthreads();
    if (t < TILE) {
        g_ps[bj * B + rowA + t] = red_n[0][t] + red_n[1][t];
        g_pp[bj * B + rowA + t] = red_p[0][t] + red_p[1][t];
    }

    if (bi < bj) {
        __syncthreads();
#pragma unroll
        for (int k = 0; k < 16; k++) {
            colN[k] += __shfl_xor_sync(0xFFFFFFFFu, colN[k], 4);
            colN[k] += __shfl_xor_sync(0xFFFFFFFFu, colN[k], 8);
            colN[k] += __shfl_xor_sync(0xFFFFFFFFu, colN[k], 16);
            colP[k] += __shfl_xor_sync(0xFFFFFFFFu, colP[k], 4);
            colP[k] += __shfl_xor_sync(0xFFFFFFFFu, colP[k], 8);
            colP[k] += __shfl_xor_sync(0xFFFFFFFFu, colP[k], 16);
        }
        if (grp == 0) {
#pragma unroll
            for (int nt = 0; nt < 8; nt++)
#pragma unroll
                for (int q = 0; q < 2; q++) {
                    int cloc = wc * 64 + nt * 8 + 2 * tig + q;
                    red_n[wr][cloc] = colN[nt * 2 + q];
                    red_p[wr][cloc] = colP[nt * 2 + q];
                }
        }
        __syncthreads();
        if (t < TILE) {
            g_ps[bi * B + rowB + t] =
                red_n[0][t] + red_n[1][t] + red_n[2][t] + red_n[3][t];
            g_pp[bi * B + rowB + t] =
                red_p[0][t] + red_p[1][t] + red_p[2][t] + red_p[3][t];
        }
    }
}

// -------- 3: final = per-row lse + contrastive closed form + finalize ------
__global__ __launch_bounds__(256) void final_kernel(const int* __restrict__ labels,
                                                    float* __restrict__ out) {
    int i = blockIdx.x * 256 + threadIdx.x;
    float SN = 0.0f, SP = 0.0f;
#pragma unroll 4
    for (int k = 0; k < NBLK; k++) {
        SN += g_ps[k * B + i];      // coalesced across lanes
        SP += g_pp[k * B + i];
    }
    float lse = MFIX + lg2a(SN) * LN2;
    float pd_cnt = g_acc[1], ct_cnt = g_acc[2];
    float Ci = (labels[i] ? pd_cnt : ct_cnt) - 1.0f;
    // sum over positives of softplus(lse_i - s) ≈ C_i*lse_i - Σs + P_i/N_i
    float contrib = Ci * lse + SP / SN;

    __shared__ float sh[256];
    float tot = block_reduce_sum(contrib, sh);
    if (threadIdx.x == 0) {
        atomicAdd(&g_acc[6], tot);
        __threadfence();
        unsigned done = atomicAdd(&g_done, 1u);
        if (done == (unsigned)(B / 256) - 1u) {
            volatile float* a = g_acc;
            float focal = a[0] / (float)B;
            float pdc = a[1], ctc = a[2];
            float pd = (pdc > 0.0f) ? a[3] / pdc : 0.0f;
            float ct = (ctc > 0.0f) ? a[4] / ctc : 0.0f;
            float ce = a[5] / (float)B;
            float reg = (pd + ct + ce) / ((float)(NR * (NR - 1)) * 0.5f + (float)NR);
            float cont = (a[6] - a[7]) / (float)B;
            out[0] = 1.0f * focal + 0.5f * cont + 0.3f * reg;
#pragma unroll
            for (int k = 0; k < 8; k++) g_acc[k] = 0.0f;
            g_done = 0u;
        }
    }
}

// -------- launch -----------------------------------------------------------
extern "C" void kernel_launch(void* const* d_in, const int* in_sizes, int n_in,
                              void* d_out, int out_size) {
    const float* logits = (const float*)d_in[0];
    const float* proj   = (const float*)d_in[1];
    const float* rp     = (const float*)d_in[2];
    const int*   labels = (const int*)d_in[3];
    float* out = (float*)d_out;
    (void)in_sizes; (void)n_in; (void)out_size;

    prep_kernel<<<B / 16, 256>>>(proj, logits, rp, labels);
    sim_kernel<<<NTRI, 256>>>(labels);
    final_kernel<<<B / 256, 256>>>(labels, out);
}

// round 12
// speedup vs baseline: 1.5000x; 1.0031x over previous
#include <cuda_runtime.h>
#include <cuda_bf16.h>
#include <math.h>
#include <stdint.h>

#define B 4096
#define D 256
#define NR 4
#define TEMP_INV 10.0f
#define TILE 128
#define NBLK 32                          // B / TILE
#define NTRI (NBLK * (NBLK + 1) / 2)     // 528 upper-tri tiles
#define LOG2E 1.4426950408889634f
#define LN2   0.6931471805599453f
#define MFIX  10.0f                      // fixed LSE max: sim in [-10,10]

#define SROWB 80u                        // smem row stride bytes (64 data + 16 pad)
#define STGB  (128u * SROWB)             // stage stride = 10240 B
#define NSTG  4                          // ring depth
#define DSMEM (2u * NSTG * STGB)         // 81920 B dynamic smem (A then B)

// -------- scratch ----------------------------------------------------------
__device__ __nv_bfloat16 g_pn[B * D];    // bf16 normalized projections (2 MB)
__device__ float g_ps[NBLK * B];         // [slot][row] negative exp-sums
__device__ float g_pp[NBLK * B];         // [slot][row] positive exp-sums
__device__ float g_acc[8];               // 0 focal,1 pd,2 ct,3 Spd,4 Sct,5 ce,6 contA,7 ssum
__device__ unsigned g_done;

// -------- helpers ----------------------------------------------------------
__device__ __forceinline__ float ex2a(float x) {
    float y; asm("ex2.approx.f32 %0, %1;" : "=f"(y) : "f"(x)); return y;
}
__device__ __forceinline__ float lg2a(float x) {
    float y; asm("lg2.approx.f32 %0, %1;" : "=f"(y) : "f"(x)); return y;
}

__device__ __forceinline__ void mma_bf16(float c[4], const uint32_t a[4],
                                         uint32_t b0, uint32_t b1) {
    asm volatile(
        "mma.sync.aligned.m16n8k16.row.col.f32.bf16.bf16.f32 "
        "{%0,%1,%2,%3}, {%4,%5,%6,%7}, {%8,%9}, {%0,%1,%2,%3};\n"
        : "+f"(c[0]), "+f"(c[1]), "+f"(c[2]), "+f"(c[3])
        : "r"(a[0]), "r"(a[1]), "r"(a[2]), "r"(a[3]), "r"(b0), "r"(b1));
}

__device__ __forceinline__ void ldsm4(uint32_t& r0, uint32_t& r1, uint32_t& r2,
                                      uint32_t& r3, uint32_t addr) {
    asm volatile("ldmatrix.sync.aligned.m8n8.x4.shared.b16 {%0,%1,%2,%3}, [%4];\n"
                 : "=r"(r0), "=r"(r1), "=r"(r2), "=r"(r3) : "r"(addr));
}

__device__ __forceinline__ void cp16(uint32_t smem_dst, const void* gsrc) {
    asm volatile("cp.async.ca.shared.global [%0], [%1], 16;\n" :: "r"(smem_dst), "l"(gsrc));
}
#define CP_COMMIT() asm volatile("cp.async.commit_group;\n" ::: "memory")
#define CP_WAIT(n)  asm volatile("cp.async.wait_group %0;\n" :: "n"(n) : "memory")

__device__ __forceinline__ void tri_decode(int idx, int& bi, int& bj) {
    int k = idx, r = 0;
#pragma unroll 1
    while (k >= NBLK - r) { k -= NBLK - r; r++; }
    bi = r; bj = r + k;
}

// -------- 1: prep = normalize + distributed focal/region -------------------
__global__ __launch_bounds__(256) void prep_kernel(const float* __restrict__ proj,
                                                   const float* __restrict__ logits,
                                                   const float* __restrict__ rp,
                                                   const int* __restrict__ labels) {
    int warp = threadIdx.x >> 5, lane = threadIdx.x & 31;
    {
        int rowA = blockIdx.x * 16 + warp;       // rows blk*16 + {0..7}
        int rowB = rowA + 8;                     // rows blk*16 + {8..15}
        const float4* pa = (const float4*)(proj + (size_t)rowA * D);
        const float4* pb = (const float4*)(proj + (size_t)rowB * D);
        float4 a1 = pa[lane], a2 = pa[32 + lane];
        float4 b1 = pb[lane], b2 = pb[32 + lane];
        float sa = a1.x * a1.x + a1.y * a1.y + a1.z * a1.z + a1.w * a1.w
                 + a2.x * a2.x + a2.y * a2.y + a2.z * a2.z + a2.w * a2.w;
        float sb = b1.x * b1.x + b1.y * b1.y + b1.z * b1.z + b1.w * b1.w
                 + b2.x * b2.x + b2.y * b2.y + b2.z * b2.z + b2.w * b2.w;
#pragma unroll
        for (int o = 16; o > 0; o >>= 1) {
            sa += __shfl_xor_sync(0xFFFFFFFFu, sa, o);
            sb += __shfl_xor_sync(0xFFFFFFFFu, sb, o);
        }
        float ia = 1.0f / fmaxf(sqrtf(sa), 1e-12f);
        float ib = 1.0f / fmaxf(sqrtf(sb), 1e-12f);
        union { __nv_bfloat162 h2[2]; uint2 u2; } c1, c2, c3, c4;
        c1.h2[0] = __floats2bfloat162_rn(a1.x * ia, a1.y * ia);
        c1.h2[1] = __floats2bfloat162_rn(a1.z * ia, a1.w * ia);
        c2.h2[0] = __floats2bfloat162_rn(a2.x * ia, a2.y * ia);
        c2.h2[1] = __floats2bfloat162_rn(a2.z * ia, a2.w * ia);
        c3.h2[0] = __floats2bfloat162_rn(b1.x * ib, b1.y * ib);
        c3.h2[1] = __floats2bfloat162_rn(b1.z * ib, b1.w * ib);
        c4.h2[0] = __floats2bfloat162_rn(b2.x * ib, b2.y * ib);
        c4.h2[1] = __floats2bfloat162_rn(b2.z * ib, b2.w * ib);
        uint2* da = (uint2*)(g_pn + (size_t)rowA * D);
        uint2* db = (uint2*)(g_pn + (size_t)rowB * D);
        da[lane] = c1.u2; da[32 + lane] = c2.u2;
        db[lane] = c3.u2; db[32 + lane] = c4.u2;
    }

    // focal + region: 16 items per block, warp 0 lanes 0..15
    if (warp == 0) {
        float focal = 0, Spd = 0, Sct = 0, ce_sum = 0, cpd = 0, cct = 0;
        if (lane < 16) {
            int b = blockIdx.x * 16 + lane;
            int y = labels[b];
            float z0 = logits[2 * b] * (LOG2E / 1.5f);
            float z1 = logits[2 * b + 1] * (LOG2E / 1.5f);
            float m  = fmaxf(z0, z1);
            float l2 = m + lg2a(ex2a(z0 - m) + ex2a(z1 - m));
            float ce = (l2 - (y ? z1 : z0)) * LN2;
            float pt = ex2a(-ce * LOG2E);
            float om = 1.0f - pt;
            focal = om * om * ce;
            if (y) cpd = 1.0f; else cct = 1.0f;

            float p[NR][2], le[NR][2], ent[NR];
#pragma unroll
            for (int r = 0; r < NR; r++) {
                float a0 = rp[((size_t)r * B + b) * 2] * LOG2E;
                float a1 = rp[((size_t)r * B + b) * 2 + 1] * LOG2E;
                float mm = fmaxf(a0, a1);
                float ll = mm + lg2a(ex2a(a0 - mm) + ex2a(a1 - mm));
                float lp0 = (a0 - ll) * LN2, lp1 = (a1 - ll) * LN2;
                p[r][0] = ex2a(a0 - ll);
                p[r][1] = ex2a(a1 - ll);
                le[r][0] = lg2a(p[r][0] + 1e-10f) * LN2;
                le[r][1] = lg2a(p[r][1] + 1e-10f) * LN2;
                ent[r] = p[r][0] * lp0 + p[r][1] * lp1;
                ce_sum += -(y ? lp1 : lp0);
            }
            float S = 0.0f;
#pragma unroll
            for (int i = 0; i < NR; i++)
#pragma unroll
                for (int j = i + 1; j < NR; j++)
                    S += ent[j] - (p[j][0] * le[i][0] + p[j][1] * le[i][1]);
            if (y) Spd = S; else Sct = S;
        }
#pragma unroll
        for (int o = 8; o > 0; o >>= 1) {
            focal  += __shfl_xor_sync(0xFFFFFFFFu, focal, o);
            cpd    += __shfl_xor_sync(0xFFFFFFFFu, cpd, o);
            cct    += __shfl_xor_sync(0xFFFFFFFFu, cct, o);
            Spd    += __shfl_xor_sync(0xFFFFFFFFu, Spd, o);
            Sct    += __shfl_xor_sync(0xFFFFFFFFu, Sct, o);
            ce_sum += __shfl_xor_sync(0xFFFFFFFFu, ce_sum, o);
        }
        if (lane == 0) {
            atomicAdd(&g_acc[0], focal);
            atomicAdd(&g_acc[1], cpd);
            atomicAdd(&g_acc[2], cct);
            atomicAdd(&g_acc[3], Spd);
            atomicAdd(&g_acc[4], Sct);
            atomicAdd(&g_acc[5], ce_sum);
        }
    }
}

// -------- 2: sim GEMM, 4-stage K32 cp.async ring (dynamic smem) ------------
__global__ __launch_bounds__(256, 2) void sim_kernel(const int* __restrict__ labels) {
    int bi, bj;
    tri_decode(blockIdx.x, bi, bj);

    extern __shared__ float dyn[];         // [A ring 40KB][B ring 40KB]
    __shared__ int   lA[TILE], lB[TILE];
    __shared__ float red_n[4][TILE], red_p[4][TILE];

    int t = threadIdx.x, lane = t & 31, warp = t >> 5;
    int wr = warp & 3, wc = warp >> 2;
    int tig = lane & 3, grp = lane >> 2;
    int rowA = bi * TILE, rowB = bj * TILE;

    if (t < TILE) lA[t] = labels[rowA + t];
    else          lB[t - TILE] = labels[rowB + (t - TILE)];

    uint32_t uA = (uint32_t)__cvta_generic_to_shared(&dyn[0]);
    uint32_t uB = uA + NSTG * STGB;
    int laneRow   = lane & 15;
    int laneChunk = (lane >> 4) * 16;
    uint32_t aBase = uA + (uint32_t)((wr * 32 + laneRow) * SROWB + laneChunk);
    uint32_t bBase = uB + (uint32_t)((wc * 64 + laneRow) * SROWB + laneChunk);

    // loader: thread t -> rows t>>2 and 64+(t>>2), 16B chunk t&3 (64B/row)
    int ldr0 = t >> 2, ldc0 = t & 3;
    uint32_t dA0 = uA + (uint32_t)(ldr0 * SROWB + ldc0 * 16);
    uint32_t dA1 = dA0 + 64 * SROWB;
    uint32_t dB0 = dA0 - uA + uB, dB1 = dA1 - uA + uB;

    float c[2][8][4];
#pragma unroll
    for (int mt = 0; mt < 2; mt++)
#pragma unroll
        for (int nt = 0; nt < 8; nt++)
#pragma unroll
            for (int q = 0; q < 4; q++) c[mt][nt][q] = 0.0f;

#define LOAD_STAGE(slot, kt)                                                                  \
    {                                                                                         \
        cp16(dA0 + (slot) * STGB, &g_pn[(size_t)(rowA + ldr0) * D + (kt) * 32 + ldc0 * 8]);   \
        cp16(dB0 + (slot) * STGB, &g_pn[(size_t)(rowB + ldr0) * D + (kt) * 32 + ldc0 * 8]);   \
        cp16(dA1 + (slot) * STGB, &g_pn[(size_t)(rowA + 64 + ldr0) * D + (kt) * 32 + ldc0 * 8]); \
        cp16(dB1 + (slot) * STGB, &g_pn[(size_t)(rowB + 64 + ldr0) * D + (kt) * 32 + ldc0 * 8]); \
        CP_COMMIT();                                                                          \
    }

    LOAD_STAGE(0, 0);
    LOAD_STAGE(1, 1);
    LOAD_STAGE(2, 2);

#pragma unroll
    for (int kt = 0; kt < 8; kt++) {       // 8 stages of K=32
        if (kt < 6)       { CP_WAIT(2); }
        else if (kt == 6) { CP_WAIT(1); }
        else              { CP_WAIT(0); }
        __syncthreads();                    // cp visibility + slot-reuse guard
        if (kt + 3 < 8) LOAD_STAGE((kt + 3) & 3, kt + 3);

        uint32_t cs = (uint32_t)(kt & 3) * STGB;
#pragma unroll
        for (int ks = 0; ks < 2; ks++) {    // two k16 halves (32 B apart)
            uint32_t ko = cs + ks * 32;
            uint32_t a[2][4];
            ldsm4(a[0][0], a[0][1], a[0][2], a[0][3], aBase + ko);
            ldsm4(a[1][0], a[1][1], a[1][2], a[1][3], aBase + ko + 16 * SROWB);
#pragma unroll
            for (int ntp = 0; ntp < 4; ntp++) {
                uint32_t b0, b1, b2, b3;
                ldsm4(b0, b1, b2, b3, bBase + ko + (uint32_t)(ntp * 16 * SROWB));
                mma_bf16(c[0][2 * ntp],     a[0], b0, b2);
                mma_bf16(c[0][2 * ntp + 1], a[0], b1, b3);
                mma_bf16(c[1][2 * ntp],     a[1], b0, b2);
                mma_bf16(c[1][2 * ntp + 1], a[1], b1, b3);
            }
        }
    }
#undef LOAD_STAGE

    // scale + diagonal mask
#pragma unroll
    for (int mt = 0; mt < 2; mt++)
#pragma unroll
        for (int nt = 0; nt < 8; nt++)
#pragma unroll
            for (int q = 0; q < 4; q++) c[mt][nt][q] *= TEMP_INV;

    if (bi == bj) {
#pragma unroll
        for (int mt = 0; mt < 2; mt++) {
            int gi0 = wr * 32 + mt * 16 + grp;
#pragma unroll
            for (int nt = 0; nt < 8; nt++) {
                int gj = wc * 64 + nt * 8 + 2 * tig;
                if (gi0 == gj)         c[mt][nt][0] = -1e9f;
                if (gi0 == gj + 1)     c[mt][nt][1] = -1e9f;
                if (gi0 + 8 == gj)     c[mt][nt][2] = -1e9f;
                if (gi0 + 8 == gj + 1) c[mt][nt][3] = -1e9f;
            }
        }
    }

    // ---- epilogue: route exp(s-10) to N / P, plus positive s-sum ----------
    float colN[16], colP[16];
#pragma unroll
    for (int k = 0; k < 16; k++) { colN[k] = 0.0f; colP[k] = 0.0f; }
    float ssum = 0.0f;

#pragma unroll
    for (int mt = 0; mt < 2; mt++) {
#pragma unroll
        for (int rr = 0; rr < 2; rr++) {
            int rloc = wr * 32 + mt * 16 + rr * 8 + grp;
            int labr = lA[rloc];
            float rn = 0.0f, rp_ = 0.0f;
#pragma unroll
            for (int nt = 0; nt < 8; nt++) {
#pragma unroll
                for (int q = 0; q < 2; q++) {
                    int cloc = wc * 64 + nt * 8 + 2 * tig + q;
                    float v = c[mt][nt][rr * 2 + q];
                    float e = ex2a((v - MFIX) * LOG2E);   // 0 at diag (v=-1e9)
                    bool pos = (lB[cloc] == labr);
                    int idx = nt * 2 + q;
                    if (pos) {
                        rp_ += e; colP[idx] += e;
                        if (v > -1e8f) ssum += v;          // exclude diag
                    } else {
                        rn += e; colN[idx] += e;
                    }
                }
            }
            rn  += __shfl_xor_sync(0xFFFFFFFFu, rn, 1);
            rn  += __shfl_xor_sync(0xFFFFFFFFu, rn, 2);
            rp_ += __shfl_xor_sync(0xFFFFFFFFu, rp_, 1);
            rp_ += __shfl_xor_sync(0xFFFFFFFFu, rp_, 2);
            if (tig == 0) { red_n[wc][rloc] = rn; red_p[wc][rloc] = rp_; }
        }
    }

    // scalar s-sum: warp reduce + one atomic per warp (ordered weight)
    {
        float w = (bi < bj) ? 2.0f : 1.0f;
#pragma unroll
        for (int o = 16; o > 0; o >>= 1) ssum += __shfl_xor_sync(0xFFFFFFFFu, ssum, o);
        if (lane == 0 && ssum != 0.0f) atomicAdd(&g_acc[7], w * ssum);
    }

    __syncthreads();
    if (t < TILE) {
        g_ps[bj * B + rowA + t] = red_n[0][t] + red_n[1][t];
        g_pp[bj * B + rowA + t] = red_p[0][t] + red_p[1][t];
    }

    if (bi < bj) {
        __syncthreads();
#pragma unroll
        for (int k = 0; k < 16; k++) {
            colN[k] += __shfl_xor_sync(0xFFFFFFFFu, colN[k], 4);
            colN[k] += __shfl_xor_sync(0xFFFFFFFFu, colN[k], 8);
            colN[k] += __shfl_xor_sync(0xFFFFFFFFu, colN[k], 16);
            colP[k] += __shfl_xor_sync(0xFFFFFFFFu, colP[k], 4);
            colP[k] += __shfl_xor_sync(0xFFFFFFFFu, colP[k], 8);
            colP[k] += __shfl_xor_sync(0xFFFFFFFFu, colP[k], 16);
        }
        if (grp == 0) {
#pragma unroll
            for (int nt = 0; nt < 8; nt++)
#pragma unroll
                for (int q = 0; q < 2; q++) {
                    int cloc = wc * 64 + nt * 8 + 2 * tig + q;
                    red_n[wr][cloc] = colN[nt * 2 + q];
                    red_p[wr][cloc] = colP[nt * 2 + q];
                }
        }
        __syncthreads();
        if (t < TILE) {
            g_ps[bi * B + rowB + t] =
                red_n[0][t] + red_n[1][t] + red_n[2][t] + red_n[3][t];
            g_pp[bi * B + rowB + t] =
                red_p[0][t] + red_p[1][t] + red_p[2][t] + red_p[3][t];
        }
    }
}

// -------- 3: final = per-row lse + contrastive closed form + finalize ------
__global__ __launch_bounds__(256) void final_kernel(const int* __restrict__ labels,
                                                    float* __restrict__ out) {
    int i = blockIdx.x * 256 + threadIdx.x;
    float SN = 0.0f, SP = 0.0f;
#pragma unroll 4
    for (int k = 0; k < NBLK; k++) {
        SN += g_ps[k * B + i];      // coalesced across lanes
        SP += g_pp[k * B + i];
    }
    float lse = MFIX + lg2a(SN) * LN2;
    float Ci = (labels[i] ? g_acc[1] : g_acc[2]) - 1.0f;
    float contrib = Ci * lse + SP / SN;   // Σ_pos softplus(lse-s) ≈ C·lse − Σs + P/N

    __shared__ float sh[256];
    int t = threadIdx.x;
    sh[t] = contrib;
    __syncthreads();
    for (int s = 128; s > 0; s >>= 1) {
        if (t < s) sh[t] += sh[t + s];
        __syncthreads();
    }
    if (t == 0) {
        atomicAdd(&g_acc[6], sh[0]);
        __threadfence();
        unsigned done = atomicAdd(&g_done, 1u);
        if (done == (unsigned)(B / 256) - 1u) {
            volatile float* a = g_acc;
            float focal = a[0] / (float)B;
            float pdc = a[1], ctc = a[2];
            float pd = (pdc > 0.0f) ? a[3] / pdc : 0.0f;
            float ct = (ctc > 0.0f) ? a[4] / ctc : 0.0f;
            float ce = a[5] / (float)B;
            float reg = (pd + ct + ce) / ((float)(NR * (NR - 1)) * 0.5f + (float)NR);
            float cont = (a[6] - a[7]) / (float)B;
            out[0] = 1.0f * focal + 0.5f * cont + 0.3f * reg;
#pragma unroll
            for (int k = 0; k < 8; k++) g_acc[k] = 0.0f;
            g_done = 0u;
        }
    }
}

// -------- launch -----------------------------------------------------------
extern "C" void kernel_launch(void* const* d_in, const int* in_sizes, int n_in,
                              void* d_out, int out_size) {
    const float* logits = (const float*)d_in[0];
    const float* proj   = (const float*)d_in[1];
    const float* rp     = (const float*)d_in[2];
    const int*   labels = (const int*)d_in[3];
    float* out = (float*)d_out;
    (void)in_sizes; (void)n_in; (void)out_size;

    static bool attr_set = false;
    if (!attr_set) {
        cudaFuncSetAttribute(sim_kernel,
                             cudaFuncAttributeMaxDynamicSharedMemorySize, DSMEM);
        attr_set = true;
    }

    prep_kernel<<<B / 16, 256>>>(proj, logits, rp, labels);
    sim_kernel<<<NTRI, 256, DSMEM>>>(labels);
    final_kernel<<<B / 256, 256>>>(labels, out);
}

// round 16
// speedup vs baseline: 1.8391x; 1.2261x over previous
#include <cuda_runtime.h>
#include <math.h>
#include <stdint.h>

#define B 4096
#define D 256
#define NR 4
#define TILE 128
#define NBLK 32                          // B / TILE
#define NTRI (NBLK * (NBLK + 1) / 2)     // 528 upper-tri tiles
#define LOG2E 1.4426950408889634f
#define LN2   0.6931471805599453f
#define MFIX  10.0f
#define SCL   (10.0f / 16129.0f)         // 10 / 127^2

#define SROWB 80u                        // smem row stride (64B data + 16B pad)
#define STGB  (128u * SROWB)             // stage stride = 10240 B
#define DSMEM (2u * 4u * STGB)           // 4 stages x (A+B) = 81920 B

// -------- scratch ----------------------------------------------------------
__device__ int8_t g_pn8[B * D];          // int8 normalized projections (1 MB)
__device__ float g_ps[NBLK * B];         // [slot][row] negative exp-sums
__device__ float g_pp[NBLK * B];         // [slot][row] positive exp-sums
__device__ float g_acc[8];               // 0 focal,1 pd,2 ct,3 Spd,4 Sct,5 ce,6 contA,7 ssum
__device__ unsigned g_done;

// -------- helpers ----------------------------------------------------------
__device__ __forceinline__ float ex2a(float x) {
    float y; asm("ex2.approx.f32 %0, %1;" : "=f"(y) : "f"(x)); return y;
}
__device__ __forceinline__ float lg2a(float x) {
    float y; asm("lg2.approx.f32 %0, %1;" : "=f"(y) : "f"(x)); return y;
}

__device__ __forceinline__ void mma_i8(int c[4], const uint32_t a[4],
                                       uint32_t b0, uint32_t b1) {
    asm volatile(
        "mma.sync.aligned.m16n8k32.row.col.s32.s8.s8.s32 "
        "{%0,%1,%2,%3}, {%4,%5,%6,%7}, {%8,%9}, {%0,%1,%2,%3};\n"
        : "+r"(c[0]), "+r"(c[1]), "+r"(c[2]), "+r"(c[3])
        : "r"(a[0]), "r"(a[1]), "r"(a[2]), "r"(a[3]), "r"(b0), "r"(b1));
}

__device__ __forceinline__ void ldsm4(uint32_t& r0, uint32_t& r1, uint32_t& r2,
                                      uint32_t& r3, uint32_t addr) {
    asm volatile("ldmatrix.sync.aligned.m8n8.x4.shared.b16 {%0,%1,%2,%3}, [%4];\n"
                 : "=r"(r0), "=r"(r1), "=r"(r2), "=r"(r3) : "r"(addr));
}

__device__ __forceinline__ void cp16(uint32_t smem_dst, const void* gsrc) {
    asm volatile("cp.async.ca.shared.global [%0], [%1], 16;\n" :: "r"(smem_dst), "l"(gsrc));
}
#define CP_COMMIT() asm volatile("cp.async.commit_group;\n" ::: "memory")
#define CP_WAIT(n)  asm volatile("cp.async.wait_group %0;\n" :: "n"(n) : "memory")

__device__ __forceinline__ void tri_decode(int idx, int& bi, int& bj) {
    int k = idx, r = 0;
#pragma unroll 1
    while (k >= NBLK - r) { k -= NBLK - r; r++; }
    bi = r; bj = r + k;
}

__device__ __forceinline__ int q8(float x) {
    int v = __float2int_rn(x * 127.0f);
    return min(127, max(-127, v));
}
__device__ __forceinline__ uint32_t pack4(float4 f, float s) {
    int v0 = q8(f.x * s), v1 = q8(f.y * s), v2 = q8(f.z * s), v3 = q8(f.w * s);
    return (uint32_t)(v0 & 255) | ((uint32_t)(v1 & 255) << 8) |
           ((uint32_t)(v2 & 255) << 16) | ((uint32_t)(v3 & 255) << 24);
}

// -------- 1: prep = normalize->int8 + distributed focal/region -------------
__global__ __launch_bounds__(256) void prep_kernel(const float* __restrict__ proj,
                                                   const float* __restrict__ logits,
                                                   const float* __restrict__ rp,
                                                   const int* __restrict__ labels) {
    int warp = threadIdx.x >> 5, lane = threadIdx.x & 31;
    {
        int rowA = blockIdx.x * 16 + warp;
        int rowB = rowA + 8;
        const float4* pa = (const float4*)(proj + (size_t)rowA * D);
        const float4* pb = (const float4*)(proj + (size_t)rowB * D);
        float4 a1 = pa[lane], a2 = pa[32 + lane];
        float4 b1 = pb[lane], b2 = pb[32 + lane];
        float sa = a1.x * a1.x + a1.y * a1.y + a1.z * a1.z + a1.w * a1.w
                 + a2.x * a2.x + a2.y * a2.y + a2.z * a2.z + a2.w * a2.w;
        float sb = b1.x * b1.x + b1.y * b1.y + b1.z * b1.z + b1.w * b1.w
                 + b2.x * b2.x + b2.y * b2.y + b2.z * b2.z + b2.w * b2.w;
#pragma unroll
        for (int o = 16; o > 0; o >>= 1) {
            sa += __shfl_xor_sync(0xFFFFFFFFu, sa, o);
            sb += __shfl_xor_sync(0xFFFFFFFFu, sb, o);
        }
        float ia = 1.0f / fmaxf(sqrtf(sa), 1e-12f);
        float ib = 1.0f / fmaxf(sqrtf(sb), 1e-12f);
        uint32_t* da = (uint32_t*)(g_pn8 + (size_t)rowA * D);
        uint32_t* db = (uint32_t*)(g_pn8 + (size_t)rowB * D);
        da[lane]      = pack4(a1, ia);
        da[32 + lane] = pack4(a2, ia);
        db[lane]      = pack4(b1, ib);
        db[32 + lane] = pack4(b2, ib);
    }

    if (warp == 0) {
        float focal = 0, Spd = 0, Sct = 0, ce_sum = 0, cpd = 0, cct = 0;
        if (lane < 16) {
            int b = blockIdx.x * 16 + lane;
            int y = labels[b];
            float z0 = logits[2 * b] * (LOG2E / 1.5f);
            float z1 = logits[2 * b + 1] * (LOG2E / 1.5f);
            float m  = fmaxf(z0, z1);
            float l2 = m + lg2a(ex2a(z0 - m) + ex2a(z1 - m));
            float ce = (l2 - (y ? z1 : z0)) * LN2;
            float pt = ex2a(-ce * LOG2E);
            float om = 1.0f - pt;
            focal = om * om * ce;
            if (y) cpd = 1.0f; else cct = 1.0f;

            float p[NR][2], le[NR][2], ent[NR];
#pragma unroll
            for (int r = 0; r < NR; r++) {
                float a0 = rp[((size_t)r * B + b) * 2] * LOG2E;
                float a1 = rp[((size_t)r * B + b) * 2 + 1] * LOG2E;
                float mm = fmaxf(a0, a1);
                float ll = mm + lg2a(ex2a(a0 - mm) + ex2a(a1 - mm));
                float lp0 = (a0 - ll) * LN2, lp1 = (a1 - ll) * LN2;
                p[r][0] = ex2a(a0 - ll);
                p[r][1] = ex2a(a1 - ll);
                le[r][0] = lg2a(p[r][0] + 1e-10f) * LN2;
                le[r][1] = lg2a(p[r][1] + 1e-10f) * LN2;
                ent[r] = p[r][0] * lp0 + p[r][1] * lp1;
                ce_sum += -(y ? lp1 : lp0);
            }
            float S = 0.0f;
#pragma unroll
            for (int i = 0; i < NR; i++)
#pragma unroll
                for (int j = i + 1; j < NR; j++)
                    S += ent[j] - (p[j][0] * le[i][0] + p[j][1] * le[i][1]);
            if (y) Spd = S; else Sct = S;
        }
#pragma unroll
        for (int o = 8; o > 0; o >>= 1) {
            focal  += __shfl_xor_sync(0xFFFFFFFFu, focal, o);
            cpd    += __shfl_xor_sync(0xFFFFFFFFu, cpd, o);
            cct    += __shfl_xor_sync(0xFFFFFFFFu, cct, o);
            Spd    += __shfl_xor_sync(0xFFFFFFFFu, Spd, o);
            Sct    += __shfl_xor_sync(0xFFFFFFFFu, Sct, o);
            ce_sum += __shfl_xor_sync(0xFFFFFFFFu, ce_sum, o);
        }
        if (lane == 0) {
            atomicAdd(&g_acc[0], focal);
            atomicAdd(&g_acc[1], cpd);
            atomicAdd(&g_acc[2], cct);
            atomicAdd(&g_acc[3], Spd);
            atomicAdd(&g_acc[4], Sct);
            atomicAdd(&g_acc[5], ce_sum);
        }
    }
}

// -------- 2: sim GEMM int8 m16n8k32 (4 stages, half the MMAs) --------------
__global__ __launch_bounds__(256, 2) void sim_kernel(const int* __restrict__ labels) {
    int bi, bj;
    tri_decode(blockIdx.x, bi, bj);

    extern __shared__ uint8_t dyn[];       // [A 4 stages 40KB][B 4 stages 40KB]
    __shared__ int   lA[TILE], lB[TILE];
    __shared__ float red_n[4][TILE], red_p[4][TILE];

    int t = threadIdx.x, lane = t & 31, warp = t >> 5;
    int wr = warp & 3, wc = warp >> 2;
    int tig = lane & 3, grp = lane >> 2;
    int rowA = bi * TILE, rowB = bj * TILE;

    if (t < TILE) lA[t] = labels[rowA + t];
    else          lB[t - TILE] = labels[rowB + (t - TILE)];

    uint32_t uA = (uint32_t)__cvta_generic_to_shared(&dyn[0]);
    uint32_t uB = uA + 4u * STGB;
    int laneRow   = lane & 15;
    int laneChunk = (lane >> 4) * 16;
    uint32_t aBase = uA + (uint32_t)((wr * 32 + laneRow) * SROWB + laneChunk);
    uint32_t bBase = uB + (uint32_t)((wc * 64 + laneRow) * SROWB + laneChunk);

    // loader: thread t -> rows t>>2 and 64+(t>>2), 16B chunk t&3 (64B/row/stage)
    int ldr0 = t >> 2, ldc0 = t & 3;
    uint32_t dA0 = uA + (uint32_t)(ldr0 * SROWB + ldc0 * 16);
    uint32_t dA1 = dA0 + 64 * SROWB;
    uint32_t dB0 = dA0 - uA + uB, dB1 = dA1 - uA + uB;

    int c[2][8][4];
#pragma unroll
    for (int mt = 0; mt < 2; mt++)
#pragma unroll
        for (int nt = 0; nt < 8; nt++)
#pragma unroll
            for (int q = 0; q < 4; q++) c[mt][nt][q] = 0;

    // stage kt covers K bytes [kt*64, kt*64+64)
#define LOAD_STAGE(kt)                                                                         \
    {                                                                                          \
        cp16(dA0 + (kt) * STGB, g_pn8 + (size_t)(rowA + ldr0) * D + (kt) * 64 + ldc0 * 16);    \
        cp16(dB0 + (kt) * STGB, g_pn8 + (size_t)(rowB + ldr0) * D + (kt) * 64 + ldc0 * 16);    \
        cp16(dA1 + (kt) * STGB, g_pn8 + (size_t)(rowA + 64 + ldr0) * D + (kt) * 64 + ldc0 * 16); \
        cp16(dB1 + (kt) * STGB, g_pn8 + (size_t)(rowB + 64 + ldr0) * D + (kt) * 64 + ldc0 * 16); \
        CP_COMMIT();                                                                           \
    }

    LOAD_STAGE(0); LOAD_STAGE(1); LOAD_STAGE(2); LOAD_STAGE(3);

#pragma unroll
    for (int kt = 0; kt < 4; kt++) {
        if (kt == 0) CP_WAIT(3); else if (kt == 1) CP_WAIT(2);
        else if (kt == 2) CP_WAIT(1); else CP_WAIT(0);
        __syncthreads();
        uint32_t cs = (uint32_t)kt * STGB;
#pragma unroll
        for (int ks = 0; ks < 2; ks++) {    // two k32 halves (32 B apart)
            uint32_t ko = cs + ks * 32;
            uint32_t a[2][4];
            ldsm4(a[0][0], a[0][1], a[0][2], a[0][3], aBase + ko);
            ldsm4(a[1][0], a[1][1], a[1][2], a[1][3], aBase + ko + 16 * SROWB);
#pragma unroll
            for (int ntp = 0; ntp < 4; ntp++) {
                uint32_t b0, b1, b2, b3;
                ldsm4(b0, b1, b2, b3, bBase + ko + (uint32_t)(ntp * 16 * SROWB));
                mma_i8(c[0][2 * ntp],     a[0], b0, b2);
                mma_i8(c[0][2 * ntp + 1], a[0], b1, b3);
                mma_i8(c[1][2 * ntp],     a[1], b0, b2);
                mma_i8(c[1][2 * ntp + 1], a[1], b1, b3);
            }
        }
    }
#undef LOAD_STAGE

    // convert accumulators to float sim values IN PLACE through the same
    // int lvalues (no type-punned pointers / no aliasing UB)
    {
        int* ci = &c[0][0][0];
#pragma unroll
        for (int i = 0; i < 64; i++)
            ci[i] = __float_as_int((float)ci[i] * SCL);
    }
#define CF(mt, nt, q) __int_as_float(c[mt][nt][q])

    if (bi == bj) {
#pragma unroll
        for (int mt = 0; mt < 2; mt++) {
            int gi0 = wr * 32 + mt * 16 + grp;
#pragma unroll
            for (int nt = 0; nt < 8; nt++) {
                int gj = wc * 64 + nt * 8 + 2 * tig;
                if (gi0 == gj)         c[mt][nt][0] = __float_as_int(-1e9f);
                if (gi0 == gj + 1)     c[mt][nt][1] = __float_as_int(-1e9f);
                if (gi0 + 8 == gj)     c[mt][nt][2] = __float_as_int(-1e9f);
                if (gi0 + 8 == gj + 1) c[mt][nt][3] = __float_as_int(-1e9f);
            }
        }
    }

    // ---- epilogue: route exp(s-10) to N / P, plus positive s-sum ----------
    float colN[16], colP[16];
#pragma unroll
    for (int k = 0; k < 16; k++) { colN[k] = 0.0f; colP[k] = 0.0f; }
    float ssum = 0.0f;

#pragma unroll
    for (int mt = 0; mt < 2; mt++) {
#pragma unroll
        for (int rr = 0; rr < 2; rr++) {
            int rloc = wr * 32 + mt * 16 + rr * 8 + grp;
            int labr = lA[rloc];
            float rn = 0.0f, rp_ = 0.0f;
#pragma unroll
            for (int nt = 0; nt < 8; nt++) {
#pragma unroll
                for (int q = 0; q < 2; q++) {
                    int cloc = wc * 64 + nt * 8 + 2 * tig + q;
                    float v = CF(mt, nt, rr * 2 + q);
                    float e = ex2a((v - MFIX) * LOG2E);   // 0 at diag (v=-1e9)
                    bool pos = (lB[cloc] == labr);
                    int idx = nt * 2 + q;
                    if (pos) {
                        rp_ += e; colP[idx] += e;
                        if (v > -1e8f) ssum += v;          // exclude diag
                    } else {
                        rn += e; colN[idx] += e;
                    }
                }
            }
            rn  += __shfl_xor_sync(0xFFFFFFFFu, rn, 1);
            rn  += __shfl_xor_sync(0xFFFFFFFFu, rn, 2);
            rp_ += __shfl_xor_sync(0xFFFFFFFFu, rp_, 1);
            rp_ += __shfl_xor_sync(0xFFFFFFFFu, rp_, 2);
            if (tig == 0) { red_n[wc][rloc] = rn; red_p[wc][rloc] = rp_; }
        }
    }

    {
        float w = (bi < bj) ? 2.0f : 1.0f;
#pragma unroll
        for (int o = 16; o > 0; o >>= 1) ssum += __shfl_xor_sync(0xFFFFFFFFu, ssum, o);
        if (lane == 0 && ssum != 0.0f) atomicAdd(&g_acc[7], w * ssum);
    }

    __syncthreads();
    if (t < TILE) {
        g_ps[bj * B + rowA + t] = red_n[0][t] + red_n[1][t];
        g_pp[bj * B + rowA + t] = red_p[0][t] + red_p[1][t];
    }

    if (bi < bj) {
        __syncthreads();
#pragma unroll
        for (int k = 0; k < 16; k++) {
            colN[k] += __shfl_xor_sync(0xFFFFFFFFu, colN[k], 4);
            colN[k] += __shfl_xor_sync(0xFFFFFFFFu, colN[k], 8);
            colN[k] += __shfl_xor_sync(0xFFFFFFFFu, colN[k], 16);
            colP[k] += __shfl_xor_sync(0xFFFFFFFFu, colP[k], 4);
            colP[k] += __shfl_xor_sync(0xFFFFFFFFu, colP[k], 8);
            colP[k] += __shfl_xor_sync(0xFFFFFFFFu, colP[k], 16);
        }
        if (grp == 0) {
#pragma unroll
            for (int nt = 0; nt < 8; nt++)
#pragma unroll
                for (int q = 0; q < 2; q++) {
                    int cloc = wc * 64 + nt * 8 + 2 * tig + q;
                    red_n[wr][cloc] = colN[nt * 2 + q];
                    red_p[wr][cloc] = colP[nt * 2 + q];
                }
        }
        __syncthreads();
        if (t < TILE) {
            g_ps[bi * B + rowB + t] =
                red_n[0][t] + red_n[1][t] + red_n[2][t] + red_n[3][t];
            g_pp[bi * B + rowB + t] =
                red_p[0][t] + red_p[1][t] + red_p[2][t] + red_p[3][t];
        }
    }
#undef CF
}

// -------- 3: final = per-row lse + contrastive closed form + finalize ------
__global__ __launch_bounds__(256) void final_kernel(const int* __restrict__ labels,
                                                    float* __restrict__ out) {
    int i = blockIdx.x * 256 + threadIdx.x;
    float SN = 0.0f, SP = 0.0f;
#pragma unroll 4
    for (int k = 0; k < NBLK; k++) {
        SN += g_ps[k * B + i];
        SP += g_pp[k * B + i];
    }
    float lse = MFIX + lg2a(SN) * LN2;
    float Ci = (labels[i] ? g_acc[1] : g_acc[2]) - 1.0f;
    float contrib = Ci * lse + SP / SN;   // Σ_pos softplus(lse-s) ≈ C·lse − Σs + P/N

    __shared__ float sh[256];
    int t = threadIdx.x;
    sh[t] = contrib;
    __syncthreads();
    for (int s = 128; s > 0; s >>= 1) {
        if (t < s) sh[t] += sh[t + s];
        __syncthreads();
    }
    if (t == 0) {
        atomicAdd(&g_acc[6], sh[0]);
        __threadfence();
        unsigned done = atomicAdd(&g_done, 1u);
        if (done == (unsigned)(B / 256) - 1u) {
            volatile float* a = g_acc;
            float focal = a[0] / (float)B;
            float pdc = a[1], ctc = a[2];
            float pd = (pdc > 0.0f) ? a[3] / pdc : 0.0f;
            float ct = (ctc > 0.0f) ? a[4] / ctc : 0.0f;
            float ce = a[5] / (float)B;
            float reg = (pd + ct + ce) / ((float)(NR * (NR - 1)) * 0.5f + (float)NR);
            float cont = (a[6] - a[7]) / (float)B;
            out[0] = 1.0f * focal + 0.5f * cont + 0.3f * reg;
#pragma unroll
            for (int k = 0; k < 8; k++) g_acc[k] = 0.0f;
            g_done = 0u;
        }
    }
}

// -------- launch -----------------------------------------------------------
extern "C" void kernel_launch(void* const* d_in, const int* in_sizes, int n_in,
                              void* d_out, int out_size) {
    const float* logits = (const float*)d_in[0];
    const float* proj   = (const float*)d_in[1];
    const float* rp     = (const float*)d_in[2];
    const int*   labels = (const int*)d_in[3];
    float* out = (float*)d_out;
    (void)in_sizes; (void)n_in; (void)out_size;

    static int attr_set = 0;
    if (!attr_set) {
        cudaFuncSetAttribute(sim_kernel,
                             cudaFuncAttributeMaxDynamicSharedMemorySize, DSMEM);
        attr_set = 1;
    }

    prep_kernel<<<B / 16, 256>>>(proj, logits, rp, labels);
    sim_kernel<<<NTRI, 256, DSMEM>>>(labels);
    final_kernel<<<B / 256, 256>>>(labels, out);
}